// round 4
// baseline (speedup 1.0000x reference)
#include <cuda_runtime.h>
#include <cstddef>

// ---------------- Problem constants ----------------
#define Bsz   2
#define Lsz   4096
#define Csz   256          // DIM == DI
#define Nst   8            // SSM state size
#define DTR_  16
#define OUTC  1200
#define SZ    (Bsz*Lsz*Csz)        // 2,097,152 floats (8 MB)
#define DBLSZ (Bsz*Lsz*32)
#define HEADSZ ((size_t)Bsz*OUTC*Lsz)  // 9,830,400

// ---------------- Scratch (static device globals; no runtime alloc) -------
__device__ float g_seq0[SZ], g_seq1[SZ];
__device__ float g_x[SZ],    g_zs[SZ];
__device__ float g_xc0[SZ],  g_xc1[SZ];
__device__ float g_dbl0[DBLSZ], g_dbl1[DBLSZ];
__device__ float g_dt0[SZ],  g_dt1[SZ];
__device__ float g_y0[SZ],   g_y1[SZ];
__device__ float g_yavg[SZ];
__device__ float g_o[SZ];
__device__ float g_rs[Bsz*Lsz];
__device__ float g_Wp[Csz*Csz];

// ---------------- LayerNorm + (b,c,l) -> (b,l,c) transpose ----------------
// grid (L/32, B, 2), block 256
__global__ __launch_bounds__(256) void ln_kernel(
    const float* __restrict__ in0, const float* __restrict__ w0, const float* __restrict__ b0,
    const float* __restrict__ in1, const float* __restrict__ w1, const float* __restrict__ b1)
{
    int which = blockIdx.z;
    const float* in = which ? in1 : in0;
    const float* w  = which ? w1  : w0;
    const float* bb = which ? b1  : b0;
    float* out = which ? g_seq1 : g_seq0;

    int b  = blockIdx.y;
    int l0 = blockIdx.x * 32;
    int t  = threadIdx.x;

    __shared__ float tile[256][33];
    __shared__ float s_mean[32], s_rstd[32];

    int cg  = t >> 3;        // 0..31
    int tl4 = (t & 7) * 4;   // 0..28

    const float* base = in + ((size_t)b * 256) * 4096 + l0;
#pragma unroll
    for (int i = 0; i < 8; i++) {
        int c = i * 32 + cg;
        float4 v = *(const float4*)(base + (size_t)c * 4096 + tl4);
        tile[c][tl4+0] = v.x; tile[c][tl4+1] = v.y;
        tile[c][tl4+2] = v.z; tile[c][tl4+3] = v.w;
    }
    __syncthreads();

    int tok = t >> 3, part = t & 7;
    float s = 0.f;
#pragma unroll 8
    for (int j = 0; j < 32; j++) s += tile[part*32 + j][tok];
    s += __shfl_xor_sync(0xffffffffu, s, 1);
    s += __shfl_xor_sync(0xffffffffu, s, 2);
    s += __shfl_xor_sync(0xffffffffu, s, 4);
    float mean = s * (1.0f/256.0f);

    float vs = 0.f;
#pragma unroll 8
    for (int j = 0; j < 32; j++) { float d = tile[part*32 + j][tok] - mean; vs += d*d; }
    vs += __shfl_xor_sync(0xffffffffu, vs, 1);
    vs += __shfl_xor_sync(0xffffffffu, vs, 2);
    vs += __shfl_xor_sync(0xffffffffu, vs, 4);
    float rstd = rsqrtf(vs * (1.0f/256.0f) + 1e-5f);

    if (part == 0) { s_mean[tok] = mean; s_rstd[tok] = rstd; }
    __syncthreads();

    float wv = w[t], bv = bb[t];
    float* ob = out + ((size_t)b * 4096 + l0) * 256 + t;
#pragma unroll 4
    for (int k = 0; k < 32; k++)
        ob[(size_t)k * 256] = (tile[t][k] - s_mean[k]) * s_rstd[k] * wv + bv;
}

// ---------------- Depthwise causal conv (K=4) + bias + silu, both dirs ----
// grid (L/16, B, 2), block 256 (thread = channel)
__global__ __launch_bounds__(256) void conv_kernel(
    const float* __restrict__ wf, const float* __restrict__ bf,
    const float* __restrict__ wb, const float* __restrict__ bbk)
{
    int dir = blockIdx.z, b = blockIdx.y, l0 = blockIdx.x * 16;
    int c = threadIdx.x;
    const float* w = dir ? wb : wf;
    float w0 = w[c*4+0], w1 = w[c*4+1], w2 = w[c*4+2], w3 = w[c*4+3];
    float bias = (dir ? bbk : bf)[c];

    float* out = (dir ? g_xc1 : g_xc0) + ((size_t)b * 4096 + l0) * 256 + c;
    const float* xb = g_x + (size_t)b * 4096 * 256 + c;

    auto LD = [&](int j) -> float {
        if (j < 0) return 0.f;
        int g = dir ? (4095 - j) : j;
        return xb[(size_t)g * 256];
    };
    float v0 = LD(l0 - 3), v1 = LD(l0 - 2), v2 = LD(l0 - 1);
#pragma unroll
    for (int i = 0; i < 16; i++) {
        float v3 = LD(l0 + i);
        float a  = w0*v0 + w1*v1 + w2*v2 + w3*v3 + bias;
        out[(size_t)i * 256] = a / (1.f + __expf(-a));
        v0 = v1; v1 = v2; v2 = v3;
    }
}

// ---------------- SSM sequential scan (both dirs), fused D-add + z gating --
// grid (8 dblocks, B, 2 dirs), block 256 (thread = (d_local, n))
__global__ __launch_bounds__(256) void scan_kernel(
    const float* __restrict__ Alog_f, const float* __restrict__ Alog_b,
    const float* __restrict__ Dp,     const float* __restrict__ Db)
{
    __shared__ float s_dt[64][32];
    __shared__ float s_x [64][32];
    __shared__ float s_z [64][32];
    __shared__ float s_B [64][8];
    __shared__ float s_C [64][8];

    int t   = threadIdx.x;
    int dl  = t >> 3, n = t & 7;
    int b   = blockIdx.y, dir = blockIdx.z;
    int dblk = blockIdx.x;
    int d   = dblk * 32 + dl;

    const float* Alog = dir ? Alog_b : Alog_f;
    float a_dn = -__expf(Alog[d * 8 + n]);
    float Dv   = (dir ? Db : Dp)[d];

    const float* dtp  = (dir ? g_dt1 : g_dt0) + ((size_t)b * 4096) * 256 + dblk * 32;
    const float* xp   = (dir ? g_xc1 : g_xc0) + ((size_t)b * 4096) * 256 + dblk * 32;
    const float* dblp = (dir ? g_dbl1 : g_dbl0) + ((size_t)b * 4096) * 32;
    const float* zp   = g_zs + ((size_t)b * 4096) * 256 + dblk * 32;
    float*       yp   = (dir ? g_y1 : g_y0) + ((size_t)b * 4096) * 256 + dblk * 32;

    float h = 0.f;
    for (int l0 = 0; l0 < 4096; l0 += 64) {
        __syncthreads();
#pragma unroll
        for (int rep = 0; rep < 8; rep++) {
            int li = rep * 8 + (t >> 5);
            int di = t & 31;
            int l  = l0 + li;
            s_dt[li][di] = dtp[(size_t)l * 256 + di];
            s_x [li][di] = xp [(size_t)l * 256 + di];
            int g = dir ? (4095 - l) : l;
            s_z [li][di] = zp[(size_t)g * 256 + di];
        }
#pragma unroll
        for (int rep = 0; rep < 4; rep++) {
            int idx = rep * 256 + t;
            int li = idx >> 4, j = idx & 15;
            float v = dblp[(size_t)(l0 + li) * 32 + 16 + j];
            if (j < 8) s_B[li][j] = v; else s_C[li][j - 8] = v;
        }
        __syncthreads();

#pragma unroll 4
        for (int li = 0; li < 64; li++) {
            float dtv = s_dt[li][dl];
            float xv  = s_x [li][dl];
            float dA  = __expf(dtv * a_dn);
            h = h * dA + (dtv * xv) * s_B[li][n];
            float yv = h * s_C[li][n];
            yv += __shfl_xor_sync(0xffffffffu, yv, 1);
            yv += __shfl_xor_sync(0xffffffffu, yv, 2);
            yv += __shfl_xor_sync(0xffffffffu, yv, 4);
            if (n == 0) {
                int l = l0 + li;
                int g = dir ? (4095 - l) : l;
                yp[(size_t)g * 256 + dl] = (yv + xv * Dv) * s_z[li][dl];
            }
        }
    }
}

// ---------------- Generic fp32 tiled GEMM:  C[m,n] = sum_k A[m,k]*W[n,k] ---
// BM=128, BN=64, BK=16, 256 threads, 8x4 microtile. Epilogues:
// 0 plain store   1 silu   2 +bias[n], softplus   3 *rowscale[m] + skip   4 conv3d-T
template<int EPI>
__global__ __launch_bounds__(256) void gemm_kernel(
    const float* __restrict__ A, int lda,
    const float* __restrict__ W, int ldw,
    int M, int N, int Kact,
    float* __restrict__ C,
    const float* __restrict__ bias,
    const float* __restrict__ rowscale,
    const float* __restrict__ skip,
    size_t outoff)
{
    __shared__ float As[16][128];
    __shared__ float Bs[16][64];

    int t  = threadIdx.x;
    int m0 = blockIdx.y * 128, n0 = blockIdx.x * 64;
    int tx = t & 15, ty = t >> 4;
    int tm = ty * 8, tn = tx * 4;
    int k4 = (t & 3) * 4;
    int rA = t >> 2;          // 0..63

    float acc[8][4];
#pragma unroll
    for (int i = 0; i < 8; i++)
#pragma unroll
        for (int j = 0; j < 4; j++) acc[i][j] = 0.f;

    for (int k0 = 0; k0 < Kact; k0 += 16) {
#pragma unroll
        for (int pass = 0; pass < 2; pass++) {
            int mi = pass * 64 + rA;
            int gm = m0 + mi;
            float4 v = make_float4(0.f, 0.f, 0.f, 0.f);
            if (gm < M) v = *(const float4*)(A + (size_t)gm * lda + k0 + k4);
            As[k4+0][mi] = v.x; As[k4+1][mi] = v.y;
            As[k4+2][mi] = v.z; As[k4+3][mi] = v.w;
        }
        {
            int gn = n0 + rA;
            float4 v = make_float4(0.f, 0.f, 0.f, 0.f);
            if (gn < N) v = *(const float4*)(W + (size_t)gn * ldw + k0 + k4);
            Bs[k4+0][rA] = v.x; Bs[k4+1][rA] = v.y;
            Bs[k4+2][rA] = v.z; Bs[k4+3][rA] = v.w;
        }
        __syncthreads();
#pragma unroll
        for (int kk = 0; kk < 16; kk++) {
            float4 a0 = *(const float4*)&As[kk][tm];
            float4 a1 = *(const float4*)&As[kk][tm + 4];
            float4 bv = *(const float4*)&Bs[kk][tn];
            float ar[8] = {a0.x,a0.y,a0.z,a0.w,a1.x,a1.y,a1.z,a1.w};
            float br[4] = {bv.x,bv.y,bv.z,bv.w};
#pragma unroll
            for (int i = 0; i < 8; i++)
#pragma unroll
                for (int j = 0; j < 4; j++)
                    acc[i][j] = fmaf(ar[i], br[j], acc[i][j]);
        }
        __syncthreads();
    }

#pragma unroll
    for (int i = 0; i < 8; i++) {
        int m = m0 + tm + i;
        if (m >= M) continue;
#pragma unroll
        for (int j = 0; j < 4; j++) {
            int n = n0 + tn + j;
            if (n >= N) continue;
            float v = acc[i][j];
            if (EPI == 0) {
                C[(size_t)m * N + n] = v;
            } else if (EPI == 1) {
                C[(size_t)m * N + n] = v / (1.f + __expf(-v));
            } else if (EPI == 2) {
                v += bias[n];
                C[(size_t)m * N + n] = (v > 20.f) ? v : log1pf(__expf(v));
            } else if (EPI == 3) {
                int bb = m >> 12, l = m & 4095;
                C[(size_t)m * N + n] =
                    v * rowscale[m] + skip[((size_t)bb * 256 + n) * 4096 + l];
            } else { // EPI == 4 : m = out-channel, n = token
                int bb = n >> 12, l = n & 4095;
                C[outoff + ((size_t)bb * OUTC + m) * 4096 + l] = v + bias[m];
            }
        }
    }
}

// ---------------- Per-row rmsnorm scale: s[m] = rsqrt(mean(y^2)+eps) -------
__global__ __launch_bounds__(256) void rms_kernel(const float* __restrict__ y,
                                                  float* __restrict__ s)
{
    int m = blockIdx.x * 8 + (threadIdx.x >> 5);
    int lane = threadIdx.x & 31;
    const float* r = y + (size_t)m * 256;
    float acc = 0.f;
#pragma unroll
    for (int j = 0; j < 8; j++) { float v = r[lane + 32 * j]; acc += v * v; }
#pragma unroll
    for (int o = 16; o; o >>= 1) acc += __shfl_xor_sync(0xffffffffu, acc, o);
    if (lane == 0) s[m] = rsqrtf(acc * (1.0f/256.0f) + 1e-5f);
}

// ---------------- y_avg = 0.5*(y_f + y_b) ----------------------------------
__global__ __launch_bounds__(256) void avg_kernel()
{
    int idx = blockIdx.x * blockDim.x + threadIdx.x;   // float4 index
    const float4* a = (const float4*)g_y0;
    const float4* b = (const float4*)g_y1;
    float4 va = a[idx], vb = b[idx];
    float4 r;
    r.x = 0.5f * (va.x + vb.x); r.y = 0.5f * (va.y + vb.y);
    r.z = 0.5f * (va.z + vb.z); r.w = 0.5f * (va.w + vb.w);
    ((float4*)g_yavg)[idx] = r;
}

// ---------------- fold rms_w into out_proj_w -------------------------------
__global__ __launch_bounds__(256) void wp_kernel(const float* __restrict__ ow,
                                                 const float* __restrict__ rw)
{
    int idx = blockIdx.x * blockDim.x + threadIdx.x;  // 65536 total
    g_Wp[idx] = ow[idx] * rw[idx & 255];
}

// ---------------- host launcher --------------------------------------------
#define DEVPTR(symname) ([&]() { void* p_ = nullptr; cudaGetSymbolAddress(&p_, symname); return (float*)p_; }())

extern "C" void kernel_launch(void* const* d_in, const int* in_sizes, int n_in,
                              void* d_out, int out_size)
{
    (void)in_sizes; (void)n_in; (void)out_size;
    const float* in0        = (const float*)d_in[0];
    const float* in1        = (const float*)d_in[1];
    const float* norm0_w    = (const float*)d_in[2];
    const float* norm0_b    = (const float*)d_in[3];
    const float* norm1_w    = (const float*)d_in[4];
    const float* norm1_b    = (const float*)d_in[5];
    const float* in_proj_w  = (const float*)d_in[6];
    const float* in_projz_w = (const float*)d_in[7];
    const float* conv1d_w   = (const float*)d_in[8];
    const float* conv1d_b   = (const float*)d_in[9];
    const float* conv1db_w  = (const float*)d_in[10];
    const float* conv1db_b  = (const float*)d_in[11];
    const float* xproj_w    = (const float*)d_in[12];
    const float* xprojb_w   = (const float*)d_in[13];
    const float* dtproj_w   = (const float*)d_in[14];
    const float* dtproj_b   = (const float*)d_in[15];
    const float* dtprojb_w  = (const float*)d_in[16];
    const float* dtprojb_b  = (const float*)d_in[17];
    const float* A_log      = (const float*)d_in[18];
    const float* Ab_log     = (const float*)d_in[19];
    const float* D_p        = (const float*)d_in[20];
    const float* D_b        = (const float*)d_in[21];
    const float* rms_w      = (const float*)d_in[22];
    const float* out_proj_w = (const float*)d_in[23];
    const float* conv3d_w   = (const float*)d_in[24];
    const float* conv3d_b   = (const float*)d_in[25];
    float* out = (float*)d_out;

    float* p_seq0 = DEVPTR(g_seq0);
    float* p_seq1 = DEVPTR(g_seq1);
    float* p_x    = DEVPTR(g_x);
    float* p_zs   = DEVPTR(g_zs);
    float* p_xc0  = DEVPTR(g_xc0);
    float* p_xc1  = DEVPTR(g_xc1);
    float* p_dbl0 = DEVPTR(g_dbl0);
    float* p_dbl1 = DEVPTR(g_dbl1);
    float* p_dt0  = DEVPTR(g_dt0);
    float* p_dt1  = DEVPTR(g_dt1);
    float* p_y0   = DEVPTR(g_y0);
    float* p_y1   = DEVPTR(g_y1);
    float* p_yavg = DEVPTR(g_yavg);
    float* p_o    = DEVPTR(g_o);
    float* p_rs   = DEVPTR(g_rs);
    float* p_Wp   = DEVPTR(g_Wp);

    // 1. layernorm + transpose (both inputs)
    ln_kernel<<<dim3(128, 2, 2), 256>>>(in0, norm0_w, norm0_b, in1, norm1_w, norm1_b);

    // 2. x = seq0 @ in_proj_w^T ; zs = silu(seq1 @ in_projz_w^T)
    gemm_kernel<0><<<dim3(4, 64), 256>>>(p_seq0, 256, in_proj_w, 256, 8192, 256, 256,
                                         p_x, nullptr, nullptr, nullptr, 0);
    gemm_kernel<1><<<dim3(4, 64), 256>>>(p_seq1, 256, in_projz_w, 256, 8192, 256, 256,
                                         p_zs, nullptr, nullptr, nullptr, 0);

    // 3. depthwise causal conv + silu, both directions
    conv_kernel<<<dim3(256, 2, 2), 256>>>(conv1d_w, conv1d_b, conv1db_w, conv1db_b);

    // 4. xproj (-> dt_raw | B | C), both directions
    gemm_kernel<0><<<dim3(1, 64), 256>>>(p_xc0, 256, xproj_w, 256, 8192, 32, 256,
                                         p_dbl0, nullptr, nullptr, nullptr, 0);
    gemm_kernel<0><<<dim3(1, 64), 256>>>(p_xc1, 256, xprojb_w, 256, 8192, 32, 256,
                                         p_dbl1, nullptr, nullptr, nullptr, 0);

    // 5. dt = softplus(dt_raw @ dtproj^T + bias), both directions
    gemm_kernel<2><<<dim3(4, 64), 256>>>(p_dbl0, 32, dtproj_w, 16, 8192, 256, 16,
                                         p_dt0, dtproj_b, nullptr, nullptr, 0);
    gemm_kernel<2><<<dim3(4, 64), 256>>>(p_dbl1, 32, dtprojb_w, 16, 8192, 256, 16,
                                         p_dt1, dtprojb_b, nullptr, nullptr, 0);

    // 6. sequential SSM scan, both directions (writes gated y in global order)
    scan_kernel<<<dim3(8, 2, 2), 256>>>(A_log, Ab_log, D_p, D_b);

    // 7. y_avg, folded out_proj weights
    avg_kernel<<<2048, 256>>>();
    wp_kernel<<<256, 256>>>(out_proj_w, rms_w);

    // 8. three heads: rms-scale -> out_proj(+skip) -> conv3d (transposed GEMM)
    float* ys[3] = { p_yavg, p_y0, p_y1 };
    for (int hh = 0; hh < 3; hh++) {
        rms_kernel<<<1024, 256>>>(ys[hh], p_rs);
        gemm_kernel<3><<<dim3(4, 64), 256>>>(ys[hh], 256, p_Wp, 256, 8192, 256, 256,
                                             p_o, nullptr, p_rs, in0, 0);
        gemm_kernel<4><<<dim3(128, 10), 256>>>(conv3d_w, 256, p_o, 256, OUTC, 8192, 256,
                                               out, conv3d_b, nullptr, nullptr,
                                               (size_t)hh * HEADSZ);
    }
}

// round 10
// speedup vs baseline: 1.3023x; 1.3023x over previous
#include <cuda_runtime.h>
#include <cuda_bf16.h>
#include <cstddef>
#include <cstdint>

// ---------------- Problem constants ----------------
#define Bsz   2
#define Lsz   4096
#define Csz   256
#define OUTC  1200
#define SZ    (Bsz*Lsz*Csz)            // 2,097,152
#define DBLSZ (Bsz*Lsz*32)
#define HEADSZ ((size_t)Bsz*OUTC*Lsz)  // 9,830,400
#define C3PAD (1280*256)               // conv3d weight padded to 1280 rows

// ---------------- Scratch (static device globals) --------------------------
__device__ float g_x[SZ], g_zs[SZ];
__device__ float g_xc0[SZ], g_xc1[SZ];
__device__ float g_dbl0[DBLSZ], g_dbl1[DBLSZ];
__device__ float g_dt0[SZ], g_dt1[SZ];
__device__ float g_y0[SZ], g_y1[SZ];
__device__ float g_skipT[SZ];
__device__ float g_rs[Bsz*Lsz];

__device__ __nv_bfloat16 g_s0h[SZ], g_s0l[SZ], g_s1h[SZ], g_s1l[SZ];
__device__ __nv_bfloat16 g_y0h[SZ], g_y0l[SZ], g_y1h[SZ], g_y1l[SZ];
__device__ __nv_bfloat16 g_yah[SZ], g_yal[SZ];
__device__ __nv_bfloat16 g_oh[SZ],  g_ol[SZ];
__device__ __nv_bfloat16 g_iph[Csz*Csz], g_ipl[Csz*Csz];
__device__ __nv_bfloat16 g_izh[Csz*Csz], g_izl[Csz*Csz];
__device__ __nv_bfloat16 g_wph[Csz*Csz], g_wpl[Csz*Csz];
__device__ __nv_bfloat16 g_c3h[C3PAD],   g_c3l[C3PAD];

// ---------------- helpers ----------------------------------------------------
__device__ __forceinline__ uint32_t smem_u32(const void* p) {
    uint32_t a;
    asm("{ .reg .u64 t; cvta.to.shared.u64 t, %1; cvt.u32.u64 %0, t; }"
        : "=r"(a) : "l"(p));
    return a;
}

#define LDSM4(r, addr) \
    asm volatile("ldmatrix.sync.aligned.m8n8.x4.shared.b16 {%0,%1,%2,%3}, [%4];" \
        : "=r"((r)[0]), "=r"((r)[1]), "=r"((r)[2]), "=r"((r)[3]) : "r"(addr))

#define MMA16816(d, a, b) \
    asm volatile("mma.sync.aligned.m16n8k16.row.col.f32.bf16.bf16.f32 " \
        "{%0,%1,%2,%3}, {%4,%5,%6,%7}, {%8,%9}, {%0,%1,%2,%3};" \
        : "+f"((d)[0]), "+f"((d)[1]), "+f"((d)[2]), "+f"((d)[3]) \
        : "r"((a)[0]), "r"((a)[1]), "r"((a)[2]), "r"((a)[3]), \
          "r"((b)[0]), "r"((b)[1]))

__device__ __forceinline__ void bsplit(float f, __nv_bfloat16* ph, __nv_bfloat16* pl, size_t i) {
    __nv_bfloat16 h = __float2bfloat16_rn(f);
    ph[i] = h;
    pl[i] = __float2bfloat16_rn(f - __bfloat162float(h));
}

// ---------------- LayerNorm + transpose + bf16 split (+skipT) ---------------
__global__ __launch_bounds__(256) void ln_kernel(
    const float* __restrict__ in0, const float* __restrict__ w0, const float* __restrict__ b0,
    const float* __restrict__ in1, const float* __restrict__ w1, const float* __restrict__ b1)
{
    int which = blockIdx.z;
    const float* in = which ? in1 : in0;
    const float* w  = which ? w1  : w0;
    const float* bb = which ? b1  : b0;
    __nv_bfloat16* oh = which ? g_s1h : g_s0h;
    __nv_bfloat16* ol = which ? g_s1l : g_s0l;

    int b = blockIdx.y, l0 = blockIdx.x * 32, t = threadIdx.x;
    __shared__ float tile[256][33];
    __shared__ float s_mean[32], s_rstd[32];

    int cg = t >> 3, tl4 = (t & 7) * 4;
    const float* base = in + ((size_t)b * 256) * 4096 + l0;
#pragma unroll
    for (int i = 0; i < 8; i++) {
        int c = i * 32 + cg;
        float4 v = *(const float4*)(base + (size_t)c * 4096 + tl4);
        tile[c][tl4+0] = v.x; tile[c][tl4+1] = v.y;
        tile[c][tl4+2] = v.z; tile[c][tl4+3] = v.w;
    }
    __syncthreads();

    int tok = t >> 3, part = t & 7;
    float s = 0.f;
#pragma unroll 8
    for (int j = 0; j < 32; j++) s += tile[part*32 + j][tok];
    s += __shfl_xor_sync(0xffffffffu, s, 1);
    s += __shfl_xor_sync(0xffffffffu, s, 2);
    s += __shfl_xor_sync(0xffffffffu, s, 4);
    float mean = s * (1.0f/256.0f);
    float vs = 0.f;
#pragma unroll 8
    for (int j = 0; j < 32; j++) { float d = tile[part*32 + j][tok] - mean; vs += d*d; }
    vs += __shfl_xor_sync(0xffffffffu, vs, 1);
    vs += __shfl_xor_sync(0xffffffffu, vs, 2);
    vs += __shfl_xor_sync(0xffffffffu, vs, 4);
    float rstd = rsqrtf(vs * (1.0f/256.0f) + 1e-5f);
    if (part == 0) { s_mean[tok] = mean; s_rstd[tok] = rstd; }
    __syncthreads();

    float wv = w[t], bv = bb[t];
    size_t idx0 = ((size_t)b * 4096 + l0) * 256 + t;
#pragma unroll 4
    for (int k = 0; k < 32; k++) {
        float raw = tile[t][k];
        float f = (raw - s_mean[k]) * s_rstd[k] * wv + bv;
        size_t idx = idx0 + (size_t)k * 256;
        bsplit(f, oh, ol, idx);
        if (which == 0) g_skipT[idx] = raw;
    }
}

// ---------------- Depthwise causal conv (K=4) + bias + silu ------------------
__global__ __launch_bounds__(256) void conv_kernel(
    const float* __restrict__ wf, const float* __restrict__ bf,
    const float* __restrict__ wb, const float* __restrict__ bbk)
{
    int dir = blockIdx.z, b = blockIdx.y, l0 = blockIdx.x * 16;
    int c = threadIdx.x;
    const float* w = dir ? wb : wf;
    float w0 = w[c*4+0], w1 = w[c*4+1], w2 = w[c*4+2], w3 = w[c*4+3];
    float bias = (dir ? bbk : bf)[c];
    float* out = (dir ? g_xc1 : g_xc0) + ((size_t)b * 4096 + l0) * 256 + c;
    const float* xb = g_x + (size_t)b * 4096 * 256 + c;
    auto LD = [&](int j) -> float {
        if (j < 0) return 0.f;
        int g = dir ? (4095 - j) : j;
        return xb[(size_t)g * 256];
    };
    float v0 = LD(l0-3), v1 = LD(l0-2), v2 = LD(l0-1);
#pragma unroll
    for (int i = 0; i < 16; i++) {
        float v3 = LD(l0 + i);
        float a = w0*v0 + w1*v1 + w2*v2 + w3*v3 + bias;
        out[(size_t)i * 256] = a / (1.f + __expf(-a));
        v0 = v1; v1 = v2; v2 = v3;
    }
}

// ---------------- SSM sequential scan -----------------------------------------
__global__ __launch_bounds__(256) void scan_kernel(
    const float* __restrict__ Alog_f, const float* __restrict__ Alog_b,
    const float* __restrict__ Dp, const float* __restrict__ Db)
{
    __shared__ float s_dt[64][32];
    __shared__ float s_x [64][32];
    __shared__ float s_z [64][32];
    __shared__ float s_B [64][8];
    __shared__ float s_C [64][8];

    int t = threadIdx.x, dl = t >> 3, n = t & 7;
    int b = blockIdx.y, dir = blockIdx.z, dblk = blockIdx.x;
    int d = dblk * 32 + dl;

    const float* Alog = dir ? Alog_b : Alog_f;
    float a_dn = -__expf(Alog[d * 8 + n]);
    float Dv   = (dir ? Db : Dp)[d];

    const float* dtp  = (dir ? g_dt1 : g_dt0) + ((size_t)b * 4096) * 256 + dblk * 32;
    const float* xp   = (dir ? g_xc1 : g_xc0) + ((size_t)b * 4096) * 256 + dblk * 32;
    const float* dblp = (dir ? g_dbl1 : g_dbl0) + ((size_t)b * 4096) * 32;
    const float* zp   = g_zs + ((size_t)b * 4096) * 256 + dblk * 32;
    float*       yp   = (dir ? g_y1 : g_y0) + ((size_t)b * 4096) * 256 + dblk * 32;

    float h = 0.f;
    for (int l0 = 0; l0 < 4096; l0 += 64) {
        __syncthreads();
#pragma unroll
        for (int rep = 0; rep < 8; rep++) {
            int li = rep * 8 + (t >> 5), di = t & 31, l = l0 + li;
            s_dt[li][di] = dtp[(size_t)l * 256 + di];
            s_x [li][di] = xp [(size_t)l * 256 + di];
            int g = dir ? (4095 - l) : l;
            s_z [li][di] = zp[(size_t)g * 256 + di];
        }
#pragma unroll
        for (int rep = 0; rep < 4; rep++) {
            int idx = rep * 256 + t, li = idx >> 4, j = idx & 15;
            float v = dblp[(size_t)(l0 + li) * 32 + 16 + j];
            if (j < 8) s_B[li][j] = v; else s_C[li][j - 8] = v;
        }
        __syncthreads();
#pragma unroll 4
        for (int li = 0; li < 64; li++) {
            float dtv = s_dt[li][dl], xv = s_x[li][dl];
            float dA = __expf(dtv * a_dn);
            h = h * dA + (dtv * xv) * s_B[li][n];
            float yv = h * s_C[li][n];
            yv += __shfl_xor_sync(0xffffffffu, yv, 1);
            yv += __shfl_xor_sync(0xffffffffu, yv, 2);
            yv += __shfl_xor_sync(0xffffffffu, yv, 4);
            if (n == 0) {
                int l = l0 + li, g = dir ? (4095 - l) : l;
                yp[(size_t)g * 256 + dl] = (yv + xv * Dv) * s_z[li][dl];
            }
        }
    }
}

// ---------------- SIMT fp32 GEMM for the tiny projections --------------------
// C[m,n] = sum_k A[m,k]*W[n,k].  EPI: 0 plain  2 +bias softplus
template<int EPI>
__global__ __launch_bounds__(256) void gemm_kernel(
    const float* __restrict__ A, int lda,
    const float* __restrict__ W, int ldw,
    int M, int N, int Kact,
    float* __restrict__ C, const float* __restrict__ bias)
{
    __shared__ float As[16][128];
    __shared__ float Bs[16][64];
    int t = threadIdx.x;
    int m0 = blockIdx.y * 128, n0 = blockIdx.x * 64;
    int tx = t & 15, ty = t >> 4, tm = ty * 8, tn = tx * 4;
    int k4 = (t & 3) * 4, rA = t >> 2;

    float acc[8][4];
#pragma unroll
    for (int i = 0; i < 8; i++)
#pragma unroll
        for (int j = 0; j < 4; j++) acc[i][j] = 0.f;

    for (int k0 = 0; k0 < Kact; k0 += 16) {
#pragma unroll
        for (int pass = 0; pass < 2; pass++) {
            int mi = pass * 64 + rA, gm = m0 + mi;
            float4 v = make_float4(0.f,0.f,0.f,0.f);
            if (gm < M) v = *(const float4*)(A + (size_t)gm * lda + k0 + k4);
            As[k4+0][mi]=v.x; As[k4+1][mi]=v.y; As[k4+2][mi]=v.z; As[k4+3][mi]=v.w;
        }
        {
            int gn = n0 + rA;
            float4 v = make_float4(0.f,0.f,0.f,0.f);
            if (gn < N) v = *(const float4*)(W + (size_t)gn * ldw + k0 + k4);
            Bs[k4+0][rA]=v.x; Bs[k4+1][rA]=v.y; Bs[k4+2][rA]=v.z; Bs[k4+3][rA]=v.w;
        }
        __syncthreads();
#pragma unroll
        for (int kk = 0; kk < 16; kk++) {
            float4 a0 = *(const float4*)&As[kk][tm];
            float4 a1 = *(const float4*)&As[kk][tm + 4];
            float4 bv = *(const float4*)&Bs[kk][tn];
            float ar[8] = {a0.x,a0.y,a0.z,a0.w,a1.x,a1.y,a1.z,a1.w};
            float br[4] = {bv.x,bv.y,bv.z,bv.w};
#pragma unroll
            for (int i = 0; i < 8; i++)
#pragma unroll
                for (int j = 0; j < 4; j++)
                    acc[i][j] = fmaf(ar[i], br[j], acc[i][j]);
        }
        __syncthreads();
    }
#pragma unroll
    for (int i = 0; i < 8; i++) {
        int m = m0 + tm + i;
        if (m >= M) continue;
#pragma unroll
        for (int j = 0; j < 4; j++) {
            int n = n0 + tn + j;
            if (n >= N) continue;
            float v = acc[i][j];
            if (EPI == 0) C[(size_t)m * N + n] = v;
            else { v += bias[n]; C[(size_t)m * N + n] = (v > 20.f) ? v : log1pf(__expf(v)); }
        }
    }
}

// ---------------- warp-MMA bf16-split GEMM (compute_103-safe HMMA) -----------
// Tile 128(M)x64(N), K=256, BK=32. 8 warps in 4x2; warp tile 32x32.
// C = Ah*Bh + Ah*Bl + Al*Bh, fp32 accum.
// A: [M][256] bf16 hi/lo, row-major. B: [N][256] bf16 hi/lo row-major (col-major B).
// EPI: 0 plain fp32   1 silu fp32
//      3 o = v*rs[m] + skipT -> bf16 split (Coh/Col), Ntot=256
//      4 out[b,oc,l] = v + bias[oc]  (m=oc, n=token)
#define HMMA_SMEM 32768
#define oAh 0u
#define oAl 10240u
#define oBh 20480u
#define oBl 25600u
#define ROWB 80u     // 40 halves per smem row

template<int EPI>
__global__ __launch_bounds__(256) void hmma_gemm(
    const __nv_bfloat16* __restrict__ Ah, const __nv_bfloat16* __restrict__ Al,
    const __nv_bfloat16* __restrict__ Bh, const __nv_bfloat16* __restrict__ Bl,
    int Ntot,
    float* __restrict__ C,
    __nv_bfloat16* __restrict__ Coh, __nv_bfloat16* __restrict__ Col,
    const float* __restrict__ rs, const float* __restrict__ skipT,
    const float* __restrict__ bias, float* __restrict__ outp, size_t outoff)
{
    extern __shared__ char sb[];
    uint32_t sb0 = smem_u32(sb);

    int t = threadIdx.x, wid = t >> 5, lane = t & 31;
    int wm = wid & 3, wn = wid >> 2;              // warp grid 4(m) x 2(n)
    int m0 = blockIdx.y * 128, n0 = blockIdx.x * 64;

    const uint4* A4h = (const uint4*)Ah;
    const uint4* A4l = (const uint4*)Al;
    const uint4* B4h = (const uint4*)Bh;
    const uint4* B4l = (const uint4*)Bl;

    float acc[2][4][4];
#pragma unroll
    for (int a = 0; a < 2; a++)
#pragma unroll
        for (int b = 0; b < 4; b++)
#pragma unroll
            for (int c = 0; c < 4; c++) acc[a][b][c] = 0.f;

    // fragment smem addresses (constant across chunks)
    uint32_t aAh[2], aAl[2], aBh[2], aBl[2];
#pragma unroll
    for (int mt = 0; mt < 2; mt++) {
        uint32_t off = (uint32_t)(wm*32 + mt*16 + (lane & 15)) * ROWB + ((lane >> 4) & 1) * 16u;
        aAh[mt] = sb0 + oAh + off;
        aAl[mt] = sb0 + oAl + off;
    }
#pragma unroll
    for (int nt = 0; nt < 2; nt++) {
        uint32_t row = (uint32_t)(wn*32 + nt*16 + (lane & 7) + ((lane >> 4) & 1) * 8);
        uint32_t off = row * ROWB + ((lane >> 3) & 1) * 16u;
        aBh[nt] = sb0 + oBh + off;
        aBl[nt] = sb0 + oBl + off;
    }

    for (int kc = 0; kc < 8; kc++) {   // 8 chunks of BK=32
        // load A tiles: 128 rows x 4 uint4, hi+lo
#pragma unroll
        for (int i = 0; i < 2; i++) {
            int u = t + i * 256, r = u >> 2, jj = u & 3;
            size_t gidx = (size_t)(m0 + r) * 32 + kc * 4 + jj;
            uint32_t so = (uint32_t)r * ROWB + jj * 16u;
            *(uint4*)(sb + oAh + so) = A4h[gidx];
            *(uint4*)(sb + oAl + so) = A4l[gidx];
        }
        // load B tiles: 64 rows x 4 uint4, hi+lo
        {
            int r = t >> 2, jj = t & 3;
            size_t gidx = (size_t)(n0 + r) * 32 + kc * 4 + jj;
            uint32_t so = (uint32_t)r * ROWB + jj * 16u;
            *(uint4*)(sb + oBh + so) = B4h[gidx];
            *(uint4*)(sb + oBl + so) = B4l[gidx];
        }
        __syncthreads();

#pragma unroll
        for (int ks = 0; ks < 2; ks++) {
            uint32_t kb = ks * 32u;   // k16 step -> 32 bytes
            uint32_t fah[2][4], fal[2][4], fbh[2][4], fbl[2][4];
#pragma unroll
            for (int mt = 0; mt < 2; mt++) {
                LDSM4(fah[mt], aAh[mt] + kb);
                LDSM4(fal[mt], aAl[mt] + kb);
            }
#pragma unroll
            for (int nt = 0; nt < 2; nt++) {
                LDSM4(fbh[nt], aBh[nt] + kb);
                LDSM4(fbl[nt], aBl[nt] + kb);
            }
#pragma unroll
            for (int mt = 0; mt < 2; mt++)
#pragma unroll
                for (int nn = 0; nn < 4; nn++) {
                    uint32_t* bh2 = &fbh[nn >> 1][(nn & 1) * 2];
                    uint32_t* bl2 = &fbl[nn >> 1][(nn & 1) * 2];
                    MMA16816(acc[mt][nn], fah[mt], bh2);
                    MMA16816(acc[mt][nn], fah[mt], bl2);
                    MMA16816(acc[mt][nn], fal[mt], bh2);
                }
        }
        __syncthreads();
    }

    // stage accumulators to smem fp32 [128][64]
    float* smemf = (float*)sb;
#pragma unroll
    for (int mt = 0; mt < 2; mt++)
#pragma unroll
        for (int nn = 0; nn < 4; nn++) {
            int row = wm*32 + mt*16 + (lane >> 2);
            int col = wn*32 + nn*8 + (lane & 3) * 2;
            smemf[row * 64 + col]       = acc[mt][nn][0];
            smemf[row * 64 + col + 1]   = acc[mt][nn][1];
            smemf[(row+8) * 64 + col]   = acc[mt][nn][2];
            smemf[(row+8) * 64 + col+1] = acc[mt][nn][3];
        }
    __syncthreads();

#pragma unroll
    for (int p = 0; p < 8; p++) {
        int row = p * 16 + (t >> 4);
        int c4  = (t & 15) * 4;
        float4 v = *(float4*)&smemf[row * 64 + c4];
        int m = m0 + row;
        if (EPI == 0) {
            *(float4*)&C[(size_t)m * Ntot + n0 + c4] = v;
        } else if (EPI == 1) {
            float4 o;
            o.x = v.x / (1.f + __expf(-v.x));
            o.y = v.y / (1.f + __expf(-v.y));
            o.z = v.z / (1.f + __expf(-v.z));
            o.w = v.w / (1.f + __expf(-v.w));
            *(float4*)&C[(size_t)m * Ntot + n0 + c4] = o;
        } else if (EPI == 3) {
            float rsm = rs[m];
            size_t base = (size_t)m * 256 + n0 + c4;
            float fv[4] = {v.x, v.y, v.z, v.w};
#pragma unroll
            for (int j = 0; j < 4; j++) {
                float f = fv[j] * rsm + skipT[base + j];
                bsplit(f, Coh, Col, base + j);
            }
        } else { // EPI == 4
            if (m < OUTC) {
                int tok = n0 + c4, bb = tok >> 12, l = tok & 4095;
                float bv = bias[m];
                float4 o = make_float4(v.x + bv, v.y + bv, v.z + bv, v.w + bv);
                *(float4*)&outp[outoff + ((size_t)(bb * OUTC + m)) * 4096 + l] = o;
            }
        }
    }
}

// ---------------- weight conversion (fold rms_w, pad conv3d) -----------------
__global__ __launch_bounds__(256) void wcvt_kernel(
    const float* __restrict__ ipw, const float* __restrict__ izw,
    const float* __restrict__ opw, const float* __restrict__ rmsw,
    const float* __restrict__ c3w)
{
    int i = blockIdx.x * 256 + threadIdx.x;   // 524288 total
    float v; __nv_bfloat16 *ph, *pl; int off;
    if (i < 65536)        { off = i;          v = ipw[off];                    ph = g_iph; pl = g_ipl; }
    else if (i < 131072)  { off = i - 65536;  v = izw[off];                    ph = g_izh; pl = g_izl; }
    else if (i < 196608)  { off = i - 131072; v = opw[off] * rmsw[off & 255];  ph = g_wph; pl = g_wpl; }
    else                  { off = i - 196608; int r = off >> 8;
                            v = (r < OUTC) ? c3w[off] : 0.f;                   ph = g_c3h; pl = g_c3l; }
    bsplit(v, ph, pl, off);
}

// ---------------- y averages + bf16 splits -----------------------------------
__global__ __launch_bounds__(256) void avgsplit_kernel()
{
    int i = blockIdx.x * 256 + threadIdx.x;   // SZ threads
    float a = g_y0[i], b = g_y1[i], m = 0.5f * (a + b);
    bsplit(a, g_y0h, g_y0l, i);
    bsplit(b, g_y1h, g_y1l, i);
    bsplit(m, g_yah, g_yal, i);
}

// ---------------- per-row rmsnorm scale --------------------------------------
__global__ __launch_bounds__(256) void rms_kernel(
    const __nv_bfloat16* __restrict__ yh, const __nv_bfloat16* __restrict__ yl,
    float* __restrict__ s)
{
    int m = blockIdx.x * 8 + (threadIdx.x >> 5);
    int lane = threadIdx.x & 31;
    size_t base = (size_t)m * 256;
    float acc = 0.f;
#pragma unroll
    for (int j = 0; j < 8; j++) {
        size_t i = base + lane + 32 * j;
        float v = __bfloat162float(yh[i]) + __bfloat162float(yl[i]);
        acc += v * v;
    }
#pragma unroll
    for (int o = 16; o; o >>= 1) acc += __shfl_xor_sync(0xffffffffu, acc, o);
    if (lane == 0) s[m] = rsqrtf(acc * (1.0f/256.0f) + 1e-5f);
}

// ---------------- host launcher ----------------------------------------------
#define DEVPTR(ty, sym) ([&]() { void* p_ = nullptr; cudaGetSymbolAddress(&p_, sym); return (ty*)p_; }())

extern "C" void kernel_launch(void* const* d_in, const int* in_sizes, int n_in,
                              void* d_out, int out_size)
{
    (void)in_sizes; (void)n_in; (void)out_size;
    const float* in0        = (const float*)d_in[0];
    const float* in1        = (const float*)d_in[1];
    const float* norm0_w    = (const float*)d_in[2];
    const float* norm0_b    = (const float*)d_in[3];
    const float* norm1_w    = (const float*)d_in[4];
    const float* norm1_b    = (const float*)d_in[5];
    const float* in_proj_w  = (const float*)d_in[6];
    const float* in_projz_w = (const float*)d_in[7];
    const float* conv1d_w   = (const float*)d_in[8];
    const float* conv1d_b   = (const float*)d_in[9];
    const float* conv1db_w  = (const float*)d_in[10];
    const float* conv1db_b  = (const float*)d_in[11];
    const float* xproj_w    = (const float*)d_in[12];
    const float* xprojb_w   = (const float*)d_in[13];
    const float* dtproj_w   = (const float*)d_in[14];
    const float* dtproj_b   = (const float*)d_in[15];
    const float* dtprojb_w  = (const float*)d_in[16];
    const float* dtprojb_b  = (const float*)d_in[17];
    const float* A_log      = (const float*)d_in[18];
    const float* Ab_log     = (const float*)d_in[19];
    const float* D_p        = (const float*)d_in[20];
    const float* D_b        = (const float*)d_in[21];
    const float* rms_w      = (const float*)d_in[22];
    const float* out_proj_w = (const float*)d_in[23];
    const float* conv3d_w   = (const float*)d_in[24];
    const float* conv3d_b   = (const float*)d_in[25];
    float* out = (float*)d_out;

    float* p_x    = DEVPTR(float, g_x);
    float* p_zs   = DEVPTR(float, g_zs);
    float* p_xc0  = DEVPTR(float, g_xc0);
    float* p_xc1  = DEVPTR(float, g_xc1);
    float* p_dbl0 = DEVPTR(float, g_dbl0);
    float* p_dbl1 = DEVPTR(float, g_dbl1);
    float* p_dt0  = DEVPTR(float, g_dt0);
    float* p_dt1  = DEVPTR(float, g_dt1);
    float* p_skT  = DEVPTR(float, g_skipT);
    float* p_rs   = DEVPTR(float, g_rs);

    __nv_bfloat16* p_s0h = DEVPTR(__nv_bfloat16, g_s0h);
    __nv_bfloat16* p_s0l = DEVPTR(__nv_bfloat16, g_s0l);
    __nv_bfloat16* p_s1h = DEVPTR(__nv_bfloat16, g_s1h);
    __nv_bfloat16* p_s1l = DEVPTR(__nv_bfloat16, g_s1l);
    __nv_bfloat16* p_y0h = DEVPTR(__nv_bfloat16, g_y0h);
    __nv_bfloat16* p_y0l = DEVPTR(__nv_bfloat16, g_y0l);
    __nv_bfloat16* p_y1h = DEVPTR(__nv_bfloat16, g_y1h);
    __nv_bfloat16* p_y1l = DEVPTR(__nv_bfloat16, g_y1l);
    __nv_bfloat16* p_yah = DEVPTR(__nv_bfloat16, g_yah);
    __nv_bfloat16* p_yal = DEVPTR(__nv_bfloat16, g_yal);
    __nv_bfloat16* p_oh  = DEVPTR(__nv_bfloat16, g_oh);
    __nv_bfloat16* p_ol  = DEVPTR(__nv_bfloat16, g_ol);
    __nv_bfloat16* p_iph = DEVPTR(__nv_bfloat16, g_iph);
    __nv_bfloat16* p_ipl = DEVPTR(__nv_bfloat16, g_ipl);
    __nv_bfloat16* p_izh = DEVPTR(__nv_bfloat16, g_izh);
    __nv_bfloat16* p_izl = DEVPTR(__nv_bfloat16, g_izl);
    __nv_bfloat16* p_wph = DEVPTR(__nv_bfloat16, g_wph);
    __nv_bfloat16* p_wpl = DEVPTR(__nv_bfloat16, g_wpl);
    __nv_bfloat16* p_c3h = DEVPTR(__nv_bfloat16, g_c3h);
    __nv_bfloat16* p_c3l = DEVPTR(__nv_bfloat16, g_c3l);

    // 0. weight conversion (independent)
    wcvt_kernel<<<2048, 256>>>(in_proj_w, in_projz_w, out_proj_w, rms_w, conv3d_w);

    // 1. layernorm + transpose + split (+skipT)
    ln_kernel<<<dim3(128, 2, 2), 256>>>(in0, norm0_w, norm0_b, in1, norm1_w, norm1_b);

    // 2. in_proj / in_projz (tensor HMMA)
    hmma_gemm<0><<<dim3(4, 64), 256, HMMA_SMEM>>>(p_s0h, p_s0l, p_iph, p_ipl, 256,
        p_x, nullptr, nullptr, nullptr, nullptr, nullptr, nullptr, 0);
    hmma_gemm<1><<<dim3(4, 64), 256, HMMA_SMEM>>>(p_s1h, p_s1l, p_izh, p_izl, 256,
        p_zs, nullptr, nullptr, nullptr, nullptr, nullptr, nullptr, 0);

    // 3. depthwise conv + silu
    conv_kernel<<<dim3(256, 2, 2), 256>>>(conv1d_w, conv1d_b, conv1db_w, conv1db_b);

    // 4. xproj (SIMT)
    gemm_kernel<0><<<dim3(1, 64), 256>>>(p_xc0, 256, xproj_w,  256, 8192, 32, 256, p_dbl0, nullptr);
    gemm_kernel<0><<<dim3(1, 64), 256>>>(p_xc1, 256, xprojb_w, 256, 8192, 32, 256, p_dbl1, nullptr);

    // 5. dtproj + softplus (SIMT)
    gemm_kernel<2><<<dim3(4, 64), 256>>>(p_dbl0, 32, dtproj_w,  16, 8192, 256, 16, p_dt0, dtproj_b);
    gemm_kernel<2><<<dim3(4, 64), 256>>>(p_dbl1, 32, dtprojb_w, 16, 8192, 256, 16, p_dt1, dtprojb_b);

    // 6. sequential scan
    scan_kernel<<<dim3(8, 2, 2), 256>>>(A_log, Ab_log, D_p, D_b);

    // 7. averages + bf16 splits of y
    avgsplit_kernel<<<SZ/256, 256>>>();

    // 8. three heads
    __nv_bfloat16* yh[3] = { p_yah, p_y0h, p_y1h };
    __nv_bfloat16* yl[3] = { p_yal, p_y0l, p_y1l };
    for (int hh = 0; hh < 3; hh++) {
        rms_kernel<<<1024, 256>>>(yh[hh], yl[hh], p_rs);
        hmma_gemm<3><<<dim3(4, 64), 256, HMMA_SMEM>>>(yh[hh], yl[hh], p_wph, p_wpl, 256,
            nullptr, p_oh, p_ol, p_rs, p_skT, nullptr, nullptr, 0);
        hmma_gemm<4><<<dim3(128, 10), 256, HMMA_SMEM>>>(p_c3h, p_c3l, p_oh, p_ol, 256,
            nullptr, nullptr, nullptr, nullptr, nullptr, conv3d_b, out, (size_t)hh * HEADSZ);
    }
}

// round 11
// speedup vs baseline: 1.3627x; 1.0464x over previous
#include <cuda_runtime.h>
#include <cuda_bf16.h>
#include <cstddef>
#include <cstdint>

// ---------------- Problem constants ----------------
#define Bsz   2
#define Lsz   4096
#define Csz   256
#define OUTC  1200
#define SZ    (Bsz*Lsz*Csz)            // 2,097,152
#define DBLSZ (Bsz*Lsz*32)
#define HEADSZ ((size_t)Bsz*OUTC*Lsz)  // 9,830,400
#define C3PAD (1280*256)               // conv3d weight padded to 1280 rows

// ---------------- Scratch (static device globals) --------------------------
__device__ float g_x[SZ], g_zs[SZ];
__device__ float g_xc0[SZ], g_xc1[SZ];
__device__ float g_dbl0[DBLSZ], g_dbl1[DBLSZ];
__device__ float g_dt0[SZ], g_dt1[SZ];
__device__ float g_y0[SZ], g_y1[SZ];
__device__ float g_skipT[SZ];
__device__ float g_rs3[3 * Bsz * Lsz];

__device__ __nv_bfloat16 g_s0h[SZ], g_s0l[SZ], g_s1h[SZ], g_s1l[SZ];
__device__ __nv_bfloat16 g_ysh[3*SZ], g_ysl[3*SZ];     // head order: avg, y0, y1
__device__ __nv_bfloat16 g_oh3[3*SZ], g_ol3[3*SZ];
__device__ __nv_bfloat16 g_iph[Csz*Csz], g_ipl[Csz*Csz];
__device__ __nv_bfloat16 g_izh[Csz*Csz], g_izl[Csz*Csz];
__device__ __nv_bfloat16 g_wph[Csz*Csz], g_wpl[Csz*Csz];
__device__ __nv_bfloat16 g_c3h[C3PAD],   g_c3l[C3PAD];

// ---------------- helpers ----------------------------------------------------
__device__ __forceinline__ uint32_t smem_u32(const void* p) {
    uint32_t a;
    asm("{ .reg .u64 t; cvta.to.shared.u64 t, %1; cvt.u32.u64 %0, t; }"
        : "=r"(a) : "l"(p));
    return a;
}

#define LDSM4(r, addr) \
    asm volatile("ldmatrix.sync.aligned.m8n8.x4.shared.b16 {%0,%1,%2,%3}, [%4];" \
        : "=r"((r)[0]), "=r"((r)[1]), "=r"((r)[2]), "=r"((r)[3]) : "r"(addr))

#define MMA16816(d, a, b) \
    asm volatile("mma.sync.aligned.m16n8k16.row.col.f32.bf16.bf16.f32 " \
        "{%0,%1,%2,%3}, {%4,%5,%6,%7}, {%8,%9}, {%0,%1,%2,%3};" \
        : "+f"((d)[0]), "+f"((d)[1]), "+f"((d)[2]), "+f"((d)[3]) \
        : "r"((a)[0]), "r"((a)[1]), "r"((a)[2]), "r"((a)[3]), \
          "r"((b)[0]), "r"((b)[1]))

#define CP_ASYNC16(dst, src) \
    asm volatile("cp.async.cg.shared.global [%0], [%1], 16;" :: "r"(dst), "l"(src))
#define CP_COMMIT() asm volatile("cp.async.commit_group;" ::: "memory")
#define CP_WAIT1()  asm volatile("cp.async.wait_group 1;" ::: "memory")
#define CP_WAIT0()  asm volatile("cp.async.wait_group 0;" ::: "memory")

__device__ __forceinline__ void bsplit(float f, __nv_bfloat16* ph, __nv_bfloat16* pl, size_t i) {
    __nv_bfloat16 h = __float2bfloat16_rn(f);
    ph[i] = h;
    pl[i] = __float2bfloat16_rn(f - __bfloat162float(h));
}

// ---------------- LayerNorm + transpose + bf16 split (+skipT) ---------------
__global__ __launch_bounds__(256) void ln_kernel(
    const float* __restrict__ in0, const float* __restrict__ w0, const float* __restrict__ b0,
    const float* __restrict__ in1, const float* __restrict__ w1, const float* __restrict__ b1)
{
    int which = blockIdx.z;
    const float* in = which ? in1 : in0;
    const float* w  = which ? w1  : w0;
    const float* bb = which ? b1  : b0;
    __nv_bfloat16* oh = which ? g_s1h : g_s0h;
    __nv_bfloat16* ol = which ? g_s1l : g_s0l;

    int b = blockIdx.y, l0 = blockIdx.x * 32, t = threadIdx.x;
    __shared__ float tile[256][33];
    __shared__ float s_mean[32], s_rstd[32];

    int cg = t >> 3, tl4 = (t & 7) * 4;
    const float* base = in + ((size_t)b * 256) * 4096 + l0;
#pragma unroll
    for (int i = 0; i < 8; i++) {
        int c = i * 32 + cg;
        float4 v = *(const float4*)(base + (size_t)c * 4096 + tl4);
        tile[c][tl4+0] = v.x; tile[c][tl4+1] = v.y;
        tile[c][tl4+2] = v.z; tile[c][tl4+3] = v.w;
    }
    __syncthreads();

    int tok = t >> 3, part = t & 7;
    float s = 0.f;
#pragma unroll 8
    for (int j = 0; j < 32; j++) s += tile[part*32 + j][tok];
    s += __shfl_xor_sync(0xffffffffu, s, 1);
    s += __shfl_xor_sync(0xffffffffu, s, 2);
    s += __shfl_xor_sync(0xffffffffu, s, 4);
    float mean = s * (1.0f/256.0f);
    float vs = 0.f;
#pragma unroll 8
    for (int j = 0; j < 32; j++) { float d = tile[part*32 + j][tok] - mean; vs += d*d; }
    vs += __shfl_xor_sync(0xffffffffu, vs, 1);
    vs += __shfl_xor_sync(0xffffffffu, vs, 2);
    vs += __shfl_xor_sync(0xffffffffu, vs, 4);
    float rstd = rsqrtf(vs * (1.0f/256.0f) + 1e-5f);
    if (part == 0) { s_mean[tok] = mean; s_rstd[tok] = rstd; }
    __syncthreads();

    float wv = w[t], bv = bb[t];
    size_t idx0 = ((size_t)b * 4096 + l0) * 256 + t;
#pragma unroll 4
    for (int k = 0; k < 32; k++) {
        float raw = tile[t][k];
        float f = (raw - s_mean[k]) * s_rstd[k] * wv + bv;
        size_t idx = idx0 + (size_t)k * 256;
        bsplit(f, oh, ol, idx);
        if (which == 0) g_skipT[idx] = raw;
    }
}

// ---------------- Depthwise causal conv (K=4) + bias + silu ------------------
__global__ __launch_bounds__(256) void conv_kernel(
    const float* __restrict__ wf, const float* __restrict__ bf,
    const float* __restrict__ wb, const float* __restrict__ bbk)
{
    int dir = blockIdx.z, b = blockIdx.y, l0 = blockIdx.x * 16;
    int c = threadIdx.x;
    const float* w = dir ? wb : wf;
    float w0 = w[c*4+0], w1 = w[c*4+1], w2 = w[c*4+2], w3 = w[c*4+3];
    float bias = (dir ? bbk : bf)[c];
    float* out = (dir ? g_xc1 : g_xc0) + ((size_t)b * 4096 + l0) * 256 + c;
    const float* xb = g_x + (size_t)b * 4096 * 256 + c;
    auto LD = [&](int j) -> float {
        if (j < 0) return 0.f;
        int g = dir ? (4095 - j) : j;
        return xb[(size_t)g * 256];
    };
    float v0 = LD(l0-3), v1 = LD(l0-2), v2 = LD(l0-1);
#pragma unroll
    for (int i = 0; i < 16; i++) {
        float v3 = LD(l0 + i);
        float a = w0*v0 + w1*v1 + w2*v2 + w3*v3 + bias;
        out[(size_t)i * 256] = a / (1.f + __expf(-a));
        v0 = v1; v1 = v2; v2 = v3;
    }
}

// ---------------- SSM sequential scan -----------------------------------------
__global__ __launch_bounds__(256) void scan_kernel(
    const float* __restrict__ Alog_f, const float* __restrict__ Alog_b,
    const float* __restrict__ Dp, const float* __restrict__ Db)
{
    __shared__ float s_dt[64][32];
    __shared__ float s_x [64][32];
    __shared__ float s_z [64][32];
    __shared__ float s_B [64][8];
    __shared__ float s_C [64][8];

    int t = threadIdx.x, dl = t >> 3, n = t & 7;
    int b = blockIdx.y, dir = blockIdx.z, dblk = blockIdx.x;
    int d = dblk * 32 + dl;

    const float* Alog = dir ? Alog_b : Alog_f;
    float a_dn = -__expf(Alog[d * 8 + n]);
    float Dv   = (dir ? Db : Dp)[d];

    const float* dtp  = (dir ? g_dt1 : g_dt0) + ((size_t)b * 4096) * 256 + dblk * 32;
    const float* xp   = (dir ? g_xc1 : g_xc0) + ((size_t)b * 4096) * 256 + dblk * 32;
    const float* dblp = (dir ? g_dbl1 : g_dbl0) + ((size_t)b * 4096) * 32;
    const float* zp   = g_zs + ((size_t)b * 4096) * 256 + dblk * 32;
    float*       yp   = (dir ? g_y1 : g_y0) + ((size_t)b * 4096) * 256 + dblk * 32;

    float h = 0.f;
    for (int l0 = 0; l0 < 4096; l0 += 64) {
        __syncthreads();
#pragma unroll
        for (int rep = 0; rep < 8; rep++) {
            int li = rep * 8 + (t >> 5), di = t & 31, l = l0 + li;
            s_dt[li][di] = dtp[(size_t)l * 256 + di];
            s_x [li][di] = xp [(size_t)l * 256 + di];
            int g = dir ? (4095 - l) : l;
            s_z [li][di] = zp[(size_t)g * 256 + di];
        }
#pragma unroll
        for (int rep = 0; rep < 4; rep++) {
            int idx = rep * 256 + t, li = idx >> 4, j = idx & 15;
            float v = dblp[(size_t)(l0 + li) * 32 + 16 + j];
            if (j < 8) s_B[li][j] = v; else s_C[li][j - 8] = v;
        }
        __syncthreads();
#pragma unroll 4
        for (int li = 0; li < 64; li++) {
            float dtv = s_dt[li][dl], xv = s_x[li][dl];
            float dA = __expf(dtv * a_dn);
            h = h * dA + (dtv * xv) * s_B[li][n];
            float yv = h * s_C[li][n];
            yv += __shfl_xor_sync(0xffffffffu, yv, 1);
            yv += __shfl_xor_sync(0xffffffffu, yv, 2);
            yv += __shfl_xor_sync(0xffffffffu, yv, 4);
            if (n == 0) {
                int l = l0 + li, g = dir ? (4095 - l) : l;
                yp[(size_t)g * 256 + dl] = (yv + xv * Dv) * s_z[li][dl];
            }
        }
    }
}

// ---------------- SIMT fp32 GEMM for the tiny projections --------------------
template<int EPI>
__global__ __launch_bounds__(256) void gemm_kernel(
    const float* __restrict__ A, int lda,
    const float* __restrict__ W, int ldw,
    int M, int N, int Kact,
    float* __restrict__ C, const float* __restrict__ bias)
{
    __shared__ float As[16][128];
    __shared__ float Bs[16][64];
    int t = threadIdx.x;
    int m0 = blockIdx.y * 128, n0 = blockIdx.x * 64;
    int tx = t & 15, ty = t >> 4, tm = ty * 8, tn = tx * 4;
    int k4 = (t & 3) * 4, rA = t >> 2;

    float acc[8][4];
#pragma unroll
    for (int i = 0; i < 8; i++)
#pragma unroll
        for (int j = 0; j < 4; j++) acc[i][j] = 0.f;

    for (int k0 = 0; k0 < Kact; k0 += 16) {
#pragma unroll
        for (int pass = 0; pass < 2; pass++) {
            int mi = pass * 64 + rA, gm = m0 + mi;
            float4 v = make_float4(0.f,0.f,0.f,0.f);
            if (gm < M) v = *(const float4*)(A + (size_t)gm * lda + k0 + k4);
            As[k4+0][mi]=v.x; As[k4+1][mi]=v.y; As[k4+2][mi]=v.z; As[k4+3][mi]=v.w;
        }
        {
            int gn = n0 + rA;
            float4 v = make_float4(0.f,0.f,0.f,0.f);
            if (gn < N) v = *(const float4*)(W + (size_t)gn * ldw + k0 + k4);
            Bs[k4+0][rA]=v.x; Bs[k4+1][rA]=v.y; Bs[k4+2][rA]=v.z; Bs[k4+3][rA]=v.w;
        }
        __syncthreads();
#pragma unroll
        for (int kk = 0; kk < 16; kk++) {
            float4 a0 = *(const float4*)&As[kk][tm];
            float4 a1 = *(const float4*)&As[kk][tm + 4];
            float4 bv = *(const float4*)&Bs[kk][tn];
            float ar[8] = {a0.x,a0.y,a0.z,a0.w,a1.x,a1.y,a1.z,a1.w};
            float br[4] = {bv.x,bv.y,bv.z,bv.w};
#pragma unroll
            for (int i = 0; i < 8; i++)
#pragma unroll
                for (int j = 0; j < 4; j++)
                    acc[i][j] = fmaf(ar[i], br[j], acc[i][j]);
        }
        __syncthreads();
    }
#pragma unroll
    for (int i = 0; i < 8; i++) {
        int m = m0 + tm + i;
        if (m >= M) continue;
#pragma unroll
        for (int j = 0; j < 4; j++) {
            int n = n0 + tn + j;
            if (n >= N) continue;
            float v = acc[i][j];
            if (EPI == 0) C[(size_t)m * N + n] = v;
            else { v += bias[n]; C[(size_t)m * N + n] = (v > 20.f) ? v : log1pf(__expf(v)); }
        }
    }
}

// ---------------- warp-MMA bf16-split GEMM, cp.async double-buffered ---------
// Tile 128(M)x64(N), K=256, BK=32, 8 warps 4x2. C = Ah*Bh + Ah*Bl + Al*Bh.
// blockIdx.z = head index (strides sA/sB applied; EPI3/4 head offsets hardwired).
// EPI: 0 plain fp32   1 silu fp32
//      3 o = v*rs[m] + skipT -> bf16 split into g_oh3/g_ol3 (+z*SZ)
//      4 out[z][b,oc,l] = v + bias[oc]
#define STG_B 30720u
#define HMMA_SMEM (2*STG_B)
#define oAh 0u
#define oAl 10240u
#define oBh 20480u
#define oBl 25600u
#define ROWB 80u

template<int EPI>
__global__ __launch_bounds__(256) void hmma_gemm(
    const __nv_bfloat16* __restrict__ Ah, const __nv_bfloat16* __restrict__ Al,
    const __nv_bfloat16* __restrict__ Bh, const __nv_bfloat16* __restrict__ Bl,
    size_t sA, size_t sB, int Ntot,
    float* __restrict__ C,
    __nv_bfloat16* __restrict__ Coh, __nv_bfloat16* __restrict__ Col,
    const float* __restrict__ rs, const float* __restrict__ skipT,
    const float* __restrict__ bias, float* __restrict__ outp)
{
    extern __shared__ char sb[];
    uint32_t sb0 = smem_u32(sb);

    int t = threadIdx.x, wid = t >> 5, lane = t & 31;
    int wm = wid & 3, wn = wid >> 2;
    int m0 = blockIdx.y * 128, n0 = blockIdx.x * 64;
    int z  = blockIdx.z;

    const uint4* A4h = (const uint4*)(Ah + (size_t)z * sA);
    const uint4* A4l = (const uint4*)(Al + (size_t)z * sA);
    const uint4* B4h = (const uint4*)(Bh + (size_t)z * sB);
    const uint4* B4l = (const uint4*)(Bl + (size_t)z * sB);

    float acc[2][4][4];
#pragma unroll
    for (int a = 0; a < 2; a++)
#pragma unroll
        for (int b = 0; b < 4; b++)
#pragma unroll
            for (int c = 0; c < 4; c++) acc[a][b][c] = 0.f;

    // fragment smem offsets (stage-relative)
    uint32_t rAh[2], rBh[2];
#pragma unroll
    for (int mt = 0; mt < 2; mt++)
        rAh[mt] = (uint32_t)(wm*32 + mt*16 + (lane & 15)) * ROWB + ((lane >> 4) & 1) * 16u;
#pragma unroll
    for (int nt = 0; nt < 2; nt++) {
        uint32_t row = (uint32_t)(wn*32 + nt*16 + (lane & 7) + ((lane >> 4) & 1) * 8);
        rBh[nt] = row * ROWB + ((lane >> 3) & 1) * 16u;
    }

    auto issue_chunk = [&](int kc, int stg) {
        uint32_t sbase = sb0 + (uint32_t)stg * STG_B;
#pragma unroll
        for (int i = 0; i < 2; i++) {
            int u = t + i * 256, r = u >> 2, jj = u & 3;
            size_t gidx = (size_t)(m0 + r) * 32 + kc * 4 + jj;
            uint32_t so = (uint32_t)r * ROWB + jj * 16u;
            CP_ASYNC16(sbase + oAh + so, A4h + gidx);
            CP_ASYNC16(sbase + oAl + so, A4l + gidx);
        }
        {
            int r = t >> 2, jj = t & 3;
            size_t gidx = (size_t)(n0 + r) * 32 + kc * 4 + jj;
            uint32_t so = (uint32_t)r * ROWB + jj * 16u;
            CP_ASYNC16(sbase + oBh + so, B4h + gidx);
            CP_ASYNC16(sbase + oBl + so, B4l + gidx);
        }
        CP_COMMIT();
    };

    issue_chunk(0, 0);
    for (int kc = 0; kc < 8; kc++) {
        if (kc < 7) { issue_chunk(kc + 1, (kc + 1) & 1); CP_WAIT1(); }
        else        { CP_WAIT0(); }
        __syncthreads();

        uint32_t sbase = sb0 + (uint32_t)(kc & 1) * STG_B;
#pragma unroll
        for (int ks = 0; ks < 2; ks++) {
            uint32_t kb = ks * 32u;
            uint32_t fah[2][4], fal[2][4], fbh[2][4], fbl[2][4];
#pragma unroll
            for (int mt = 0; mt < 2; mt++) {
                LDSM4(fah[mt], sbase + oAh + rAh[mt] + kb);
                LDSM4(fal[mt], sbase + oAl + rAh[mt] + kb);
            }
#pragma unroll
            for (int nt = 0; nt < 2; nt++) {
                LDSM4(fbh[nt], sbase + oBh + rBh[nt] + kb);
                LDSM4(fbl[nt], sbase + oBl + rBh[nt] + kb);
            }
#pragma unroll
            for (int mt = 0; mt < 2; mt++)
#pragma unroll
                for (int nn = 0; nn < 4; nn++) {
                    uint32_t* bh2 = &fbh[nn >> 1][(nn & 1) * 2];
                    uint32_t* bl2 = &fbl[nn >> 1][(nn & 1) * 2];
                    MMA16816(acc[mt][nn], fah[mt], bh2);
                    MMA16816(acc[mt][nn], fah[mt], bl2);
                    MMA16816(acc[mt][nn], fal[mt], bh2);
                }
        }
        __syncthreads();
    }

    // stage accumulators to smem fp32 [128][64]
    float* smemf = (float*)sb;
#pragma unroll
    for (int mt = 0; mt < 2; mt++)
#pragma unroll
        for (int nn = 0; nn < 4; nn++) {
            int row = wm*32 + mt*16 + (lane >> 2);
            int col = wn*32 + nn*8 + (lane & 3) * 2;
            smemf[row * 64 + col]       = acc[mt][nn][0];
            smemf[row * 64 + col + 1]   = acc[mt][nn][1];
            smemf[(row+8) * 64 + col]   = acc[mt][nn][2];
            smemf[(row+8) * 64 + col+1] = acc[mt][nn][3];
        }
    __syncthreads();

#pragma unroll
    for (int p = 0; p < 8; p++) {
        int row = p * 16 + (t >> 4);
        int c4  = (t & 15) * 4;
        float4 v = *(float4*)&smemf[row * 64 + c4];
        int m = m0 + row;
        if (EPI == 0) {
            *(float4*)&C[(size_t)m * Ntot + n0 + c4] = v;
        } else if (EPI == 1) {
            float4 o;
            o.x = v.x / (1.f + __expf(-v.x));
            o.y = v.y / (1.f + __expf(-v.y));
            o.z = v.z / (1.f + __expf(-v.z));
            o.w = v.w / (1.f + __expf(-v.w));
            *(float4*)&C[(size_t)m * Ntot + n0 + c4] = o;
        } else if (EPI == 3) {
            float rsm = rs[(size_t)z * (Bsz*Lsz) + m];
            size_t base = (size_t)m * 256 + n0 + c4;
            size_t obase = (size_t)z * SZ + base;
            float fv[4] = {v.x, v.y, v.z, v.w};
#pragma unroll
            for (int j = 0; j < 4; j++) {
                float f = fv[j] * rsm + skipT[base + j];
                bsplit(f, Coh, Col, obase + j);
            }
        } else { // EPI == 4
            if (m < OUTC) {
                int tok = n0 + c4, bb = tok >> 12, l = tok & 4095;
                float bv = bias[m];
                float4 o = make_float4(v.x + bv, v.y + bv, v.z + bv, v.w + bv);
                *(float4*)&outp[(size_t)z * HEADSZ +
                                ((size_t)(bb * OUTC + m)) * 4096 + l] = o;
            }
        }
    }
}

// ---------------- weight conversion (fold rms_w, pad conv3d) -----------------
__global__ __launch_bounds__(256) void wcvt_kernel(
    const float* __restrict__ ipw, const float* __restrict__ izw,
    const float* __restrict__ opw, const float* __restrict__ rmsw,
    const float* __restrict__ c3w)
{
    int i = blockIdx.x * 256 + threadIdx.x;   // 524288 total
    float v; __nv_bfloat16 *ph, *pl; int off;
    if (i < 65536)        { off = i;          v = ipw[off];                    ph = g_iph; pl = g_ipl; }
    else if (i < 131072)  { off = i - 65536;  v = izw[off];                    ph = g_izh; pl = g_izl; }
    else if (i < 196608)  { off = i - 131072; v = opw[off] * rmsw[off & 255];  ph = g_wph; pl = g_wpl; }
    else                  { off = i - 196608; int r = off >> 8;
                            v = (r < OUTC) ? c3w[off] : 0.f;                   ph = g_c3h; pl = g_c3l; }
    bsplit(v, ph, pl, off);
}

// ---------------- y averages + bf16 splits (3 heads contiguous) --------------
__global__ __launch_bounds__(256) void avgsplit_kernel()
{
    int i = blockIdx.x * 256 + threadIdx.x;   // SZ threads
    float a = g_y0[i], b = g_y1[i], m = 0.5f * (a + b);
    bsplit(m, g_ysh, g_ysl, i);                 // head 0: avg
    bsplit(a, g_ysh, g_ysl, (size_t)SZ + i);    // head 1: forward
    bsplit(b, g_ysh, g_ysl, (size_t)2*SZ + i);  // head 2: backward
}

// ---------------- per-row rmsnorm scale (3 heads) -----------------------------
__global__ __launch_bounds__(256) void rms_kernel(float* __restrict__ s)
{
    int hh = blockIdx.y;
    int m = blockIdx.x * 8 + (threadIdx.x >> 5);
    int lane = threadIdx.x & 31;
    size_t base = (size_t)hh * SZ + (size_t)m * 256;
    float acc = 0.f;
#pragma unroll
    for (int j = 0; j < 8; j++) {
        size_t i = base + lane + 32 * j;
        float v = __bfloat162float(g_ysh[i]) + __bfloat162float(g_ysl[i]);
        acc += v * v;
    }
#pragma unroll
    for (int o = 16; o; o >>= 1) acc += __shfl_xor_sync(0xffffffffu, acc, o);
    if (lane == 0) s[(size_t)hh * (Bsz*Lsz) + m] = rsqrtf(acc * (1.0f/256.0f) + 1e-5f);
}

// ---------------- host launcher ----------------------------------------------
#define DEVPTR(ty, sym) ([&]() { void* p_ = nullptr; cudaGetSymbolAddress(&p_, sym); return (ty*)p_; }())

extern "C" void kernel_launch(void* const* d_in, const int* in_sizes, int n_in,
                              void* d_out, int out_size)
{
    (void)in_sizes; (void)n_in; (void)out_size;
    const float* in0        = (const float*)d_in[0];
    const float* in1        = (const float*)d_in[1];
    const float* norm0_w    = (const float*)d_in[2];
    const float* norm0_b    = (const float*)d_in[3];
    const float* norm1_w    = (const float*)d_in[4];
    const float* norm1_b    = (const float*)d_in[5];
    const float* in_proj_w  = (const float*)d_in[6];
    const float* in_projz_w = (const float*)d_in[7];
    const float* conv1d_w   = (const float*)d_in[8];
    const float* conv1d_b   = (const float*)d_in[9];
    const float* conv1db_w  = (const float*)d_in[10];
    const float* conv1db_b  = (const float*)d_in[11];
    const float* xproj_w    = (const float*)d_in[12];
    const float* xprojb_w   = (const float*)d_in[13];
    const float* dtproj_w   = (const float*)d_in[14];
    const float* dtproj_b   = (const float*)d_in[15];
    const float* dtprojb_w  = (const float*)d_in[16];
    const float* dtprojb_b  = (const float*)d_in[17];
    const float* A_log      = (const float*)d_in[18];
    const float* Ab_log     = (const float*)d_in[19];
    const float* D_p        = (const float*)d_in[20];
    const float* D_b        = (const float*)d_in[21];
    const float* rms_w      = (const float*)d_in[22];
    const float* out_proj_w = (const float*)d_in[23];
    const float* conv3d_w   = (const float*)d_in[24];
    const float* conv3d_b   = (const float*)d_in[25];
    float* out = (float*)d_out;

    float* p_x    = DEVPTR(float, g_x);
    float* p_zs   = DEVPTR(float, g_zs);
    float* p_xc0  = DEVPTR(float, g_xc0);
    float* p_xc1  = DEVPTR(float, g_xc1);
    float* p_dbl0 = DEVPTR(float, g_dbl0);
    float* p_dbl1 = DEVPTR(float, g_dbl1);
    float* p_dt0  = DEVPTR(float, g_dt0);
    float* p_dt1  = DEVPTR(float, g_dt1);
    float* p_skT  = DEVPTR(float, g_skipT);
    float* p_rs3  = DEVPTR(float, g_rs3);

    __nv_bfloat16* p_s0h = DEVPTR(__nv_bfloat16, g_s0h);
    __nv_bfloat16* p_s0l = DEVPTR(__nv_bfloat16, g_s0l);
    __nv_bfloat16* p_s1h = DEVPTR(__nv_bfloat16, g_s1h);
    __nv_bfloat16* p_s1l = DEVPTR(__nv_bfloat16, g_s1l);
    __nv_bfloat16* p_ysh = DEVPTR(__nv_bfloat16, g_ysh);
    __nv_bfloat16* p_ysl = DEVPTR(__nv_bfloat16, g_ysl);
    __nv_bfloat16* p_oh3 = DEVPTR(__nv_bfloat16, g_oh3);
    __nv_bfloat16* p_ol3 = DEVPTR(__nv_bfloat16, g_ol3);
    __nv_bfloat16* p_iph = DEVPTR(__nv_bfloat16, g_iph);
    __nv_bfloat16* p_ipl = DEVPTR(__nv_bfloat16, g_ipl);
    __nv_bfloat16* p_izh = DEVPTR(__nv_bfloat16, g_izh);
    __nv_bfloat16* p_izl = DEVPTR(__nv_bfloat16, g_izl);
    __nv_bfloat16* p_wph = DEVPTR(__nv_bfloat16, g_wph);
    __nv_bfloat16* p_wpl = DEVPTR(__nv_bfloat16, g_wpl);
    __nv_bfloat16* p_c3h = DEVPTR(__nv_bfloat16, g_c3h);
    __nv_bfloat16* p_c3l = DEVPTR(__nv_bfloat16, g_c3l);

    static bool attr_done = false;
    if (!attr_done) {
        cudaFuncSetAttribute(hmma_gemm<0>, cudaFuncAttributeMaxDynamicSharedMemorySize, HMMA_SMEM);
        cudaFuncSetAttribute(hmma_gemm<1>, cudaFuncAttributeMaxDynamicSharedMemorySize, HMMA_SMEM);
        cudaFuncSetAttribute(hmma_gemm<3>, cudaFuncAttributeMaxDynamicSharedMemorySize, HMMA_SMEM);
        cudaFuncSetAttribute(hmma_gemm<4>, cudaFuncAttributeMaxDynamicSharedMemorySize, HMMA_SMEM);
        attr_done = true;
    }

    // 0. weight conversion (independent)
    wcvt_kernel<<<2048, 256>>>(in_proj_w, in_projz_w, out_proj_w, rms_w, conv3d_w);

    // 1. layernorm + transpose + split (+skipT)
    ln_kernel<<<dim3(128, 2, 2), 256>>>(in0, norm0_w, norm0_b, in1, norm1_w, norm1_b);

    // 2. in_proj / in_projz (HMMA, cp.async pipelined)
    hmma_gemm<0><<<dim3(4, 64, 1), 256, HMMA_SMEM>>>(p_s0h, p_s0l, p_iph, p_ipl, 0, 0, 256,
        p_x, nullptr, nullptr, nullptr, nullptr, nullptr, nullptr);
    hmma_gemm<1><<<dim3(4, 64, 1), 256, HMMA_SMEM>>>(p_s1h, p_s1l, p_izh, p_izl, 0, 0, 256,
        p_zs, nullptr, nullptr, nullptr, nullptr, nullptr, nullptr);

    // 3. depthwise conv + silu
    conv_kernel<<<dim3(256, 2, 2), 256>>>(conv1d_w, conv1d_b, conv1db_w, conv1db_b);

    // 4. xproj (SIMT)
    gemm_kernel<0><<<dim3(1, 64), 256>>>(p_xc0, 256, xproj_w,  256, 8192, 32, 256, p_dbl0, nullptr);
    gemm_kernel<0><<<dim3(1, 64), 256>>>(p_xc1, 256, xprojb_w, 256, 8192, 32, 256, p_dbl1, nullptr);

    // 5. dtproj + softplus (SIMT)
    gemm_kernel<2><<<dim3(4, 64), 256>>>(p_dbl0, 32, dtproj_w,  16, 8192, 256, 16, p_dt0, dtproj_b);
    gemm_kernel<2><<<dim3(4, 64), 256>>>(p_dbl1, 32, dtprojb_w, 16, 8192, 256, 16, p_dt1, dtprojb_b);

    // 6. sequential scan
    scan_kernel<<<dim3(8, 2, 2), 256>>>(A_log, Ab_log, D_p, D_b);

    // 7. averages + bf16 splits of y (3 heads contiguous)
    avgsplit_kernel<<<SZ/256, 256>>>();

    // 8. all three heads batched: rms -> out_proj(+skip) -> conv3d
    rms_kernel<<<dim3(1024, 3), 256>>>(p_rs3);
    hmma_gemm<3><<<dim3(4, 64, 3), 256, HMMA_SMEM>>>(p_ysh, p_ysl, p_wph, p_wpl,
        (size_t)SZ, 0, 256,
        nullptr, p_oh3, p_ol3, p_rs3, p_skT, nullptr, nullptr);
    hmma_gemm<4><<<dim3(128, 10, 3), 256, HMMA_SMEM>>>(p_c3h, p_c3l, p_oh3, p_ol3,
        0, (size_t)SZ, 256,
        nullptr, nullptr, nullptr, nullptr, nullptr, conv3d_b, out);
}

// round 12
// speedup vs baseline: 1.4331x; 1.0517x over previous
#include <cuda_runtime.h>
#include <cuda_bf16.h>
#include <cstddef>
#include <cstdint>

// ---------------- Problem constants ----------------
#define Bsz   2
#define Lsz   4096
#define Csz   256
#define OUTC  1200
#define SZ    (Bsz*Lsz*Csz)            // 2,097,152
#define DBLSZ (Bsz*Lsz*32)
#define HEADSZ ((size_t)Bsz*OUTC*Lsz)  // 9,830,400
#define C3PAD (1280*256)
#define WSZ   (Csz*Csz)                // 65536

// ---------------- Scratch (static device globals) --------------------------
__device__ float g_x[SZ], g_zs[SZ];
__device__ float g_xc0[SZ], g_xc1[SZ];
__device__ float g_dbl0[DBLSZ], g_dbl1[DBLSZ];
__device__ float g_dt0[SZ], g_dt1[SZ];
__device__ float g_y0[SZ], g_y1[SZ];
__device__ float g_skipT[SZ];
__device__ float g_rs3[3 * Bsz * Lsz];

__device__ __nv_bfloat16 g_sAh[2*SZ], g_sAl[2*SZ];     // seq0 | seq1
__device__ __nv_bfloat16 g_ysh[3*SZ], g_ysl[3*SZ];     // avg | y0 | y1
__device__ __nv_bfloat16 g_oh3[3*SZ], g_ol3[3*SZ];
__device__ __nv_bfloat16 g_ipzh[2*WSZ], g_ipzl[2*WSZ]; // in_proj | in_projz
__device__ __nv_bfloat16 g_wph[WSZ], g_wpl[WSZ];
__device__ __nv_bfloat16 g_c3h[C3PAD], g_c3l[C3PAD];

// ---------------- helpers ----------------------------------------------------
__device__ __forceinline__ uint32_t smem_u32(const void* p) {
    uint32_t a;
    asm("{ .reg .u64 t; cvta.to.shared.u64 t, %1; cvt.u32.u64 %0, t; }"
        : "=r"(a) : "l"(p));
    return a;
}

#define LDSM4(r, addr) \
    asm volatile("ldmatrix.sync.aligned.m8n8.x4.shared.b16 {%0,%1,%2,%3}, [%4];" \
        : "=r"((r)[0]), "=r"((r)[1]), "=r"((r)[2]), "=r"((r)[3]) : "r"(addr))

#define MMA16816(d, a, b) \
    asm volatile("mma.sync.aligned.m16n8k16.row.col.f32.bf16.bf16.f32 " \
        "{%0,%1,%2,%3}, {%4,%5,%6,%7}, {%8,%9}, {%0,%1,%2,%3};" \
        : "+f"((d)[0]), "+f"((d)[1]), "+f"((d)[2]), "+f"((d)[3]) \
        : "r"((a)[0]), "r"((a)[1]), "r"((a)[2]), "r"((a)[3]), \
          "r"((b)[0]), "r"((b)[1]))

#define CP_ASYNC16(dst, src) \
    asm volatile("cp.async.cg.shared.global [%0], [%1], 16;" :: "r"(dst), "l"(src))
#define CP_COMMIT() asm volatile("cp.async.commit_group;" ::: "memory")
#define CP_WAIT1()  asm volatile("cp.async.wait_group 1;" ::: "memory")
#define CP_WAIT0()  asm volatile("cp.async.wait_group 0;" ::: "memory")

__device__ __forceinline__ void bsplit(float f, __nv_bfloat16* ph, __nv_bfloat16* pl, size_t i) {
    __nv_bfloat16 h = __float2bfloat16_rn(f);
    ph[i] = h;
    pl[i] = __float2bfloat16_rn(f - __bfloat162float(h));
}

// ---------------- LayerNorm + transpose + bf16 split (+skipT) ---------------
__global__ __launch_bounds__(256) void ln_kernel(
    const float* __restrict__ in0, const float* __restrict__ w0, const float* __restrict__ b0,
    const float* __restrict__ in1, const float* __restrict__ w1, const float* __restrict__ b1)
{
    int which = blockIdx.z;
    const float* in = which ? in1 : in0;
    const float* w  = which ? w1  : w0;
    const float* bb = which ? b1  : b0;
    __nv_bfloat16* oh = g_sAh + (size_t)which * SZ;
    __nv_bfloat16* ol = g_sAl + (size_t)which * SZ;

    int b = blockIdx.y, l0 = blockIdx.x * 32, t = threadIdx.x;
    __shared__ float tile[256][33];
    __shared__ float s_mean[32], s_rstd[32];

    int cg = t >> 3, tl4 = (t & 7) * 4;
    const float* base = in + ((size_t)b * 256) * 4096 + l0;
#pragma unroll
    for (int i = 0; i < 8; i++) {
        int c = i * 32 + cg;
        float4 v = *(const float4*)(base + (size_t)c * 4096 + tl4);
        tile[c][tl4+0] = v.x; tile[c][tl4+1] = v.y;
        tile[c][tl4+2] = v.z; tile[c][tl4+3] = v.w;
    }
    __syncthreads();

    int tok = t >> 3, part = t & 7;
    float s = 0.f;
#pragma unroll 8
    for (int j = 0; j < 32; j++) s += tile[part*32 + j][tok];
    s += __shfl_xor_sync(0xffffffffu, s, 1);
    s += __shfl_xor_sync(0xffffffffu, s, 2);
    s += __shfl_xor_sync(0xffffffffu, s, 4);
    float mean = s * (1.0f/256.0f);
    float vs = 0.f;
#pragma unroll 8
    for (int j = 0; j < 32; j++) { float d = tile[part*32 + j][tok] - mean; vs += d*d; }
    vs += __shfl_xor_sync(0xffffffffu, vs, 1);
    vs += __shfl_xor_sync(0xffffffffu, vs, 2);
    vs += __shfl_xor_sync(0xffffffffu, vs, 4);
    float rstd = rsqrtf(vs * (1.0f/256.0f) + 1e-5f);
    if (part == 0) { s_mean[tok] = mean; s_rstd[tok] = rstd; }
    __syncthreads();

    float wv = w[t], bv = bb[t];
    size_t idx0 = ((size_t)b * 4096 + l0) * 256 + t;
#pragma unroll 4
    for (int k = 0; k < 32; k++) {
        float raw = tile[t][k];
        float f = (raw - s_mean[k]) * s_rstd[k] * wv + bv;
        size_t idx = idx0 + (size_t)k * 256;
        bsplit(f, oh, ol, idx);
        if (which == 0) g_skipT[idx] = raw;
    }
}

// ---------------- Depthwise causal conv (K=4) + bias + silu ------------------
__global__ __launch_bounds__(256) void conv_kernel(
    const float* __restrict__ wf, const float* __restrict__ bf,
    const float* __restrict__ wb, const float* __restrict__ bbk)
{
    int dir = blockIdx.z, b = blockIdx.y, l0 = blockIdx.x * 16;
    int c = threadIdx.x;
    const float* w = dir ? wb : wf;
    float w0 = w[c*4+0], w1 = w[c*4+1], w2 = w[c*4+2], w3 = w[c*4+3];
    float bias = (dir ? bbk : bf)[c];
    float* out = (dir ? g_xc1 : g_xc0) + ((size_t)b * 4096 + l0) * 256 + c;
    const float* xb = g_x + (size_t)b * 4096 * 256 + c;
    auto LD = [&](int j) -> float {
        if (j < 0) return 0.f;
        int g = dir ? (4095 - j) : j;
        return xb[(size_t)g * 256];
    };
    float v0 = LD(l0-3), v1 = LD(l0-2), v2 = LD(l0-1);
#pragma unroll
    for (int i = 0; i < 16; i++) {
        float v3 = LD(l0 + i);
        float a = w0*v0 + w1*v1 + w2*v2 + w3*v3 + bias;
        out[(size_t)i * 256] = a / (1.f + __expf(-a));
        v0 = v1; v1 = v2; v2 = v3;
    }
}

// ---------------- SSM sequential scan -----------------------------------------
__global__ __launch_bounds__(256) void scan_kernel(
    const float* __restrict__ Alog_f, const float* __restrict__ Alog_b,
    const float* __restrict__ Dp, const float* __restrict__ Db)
{
    __shared__ float s_dt[64][32];
    __shared__ float s_x [64][32];
    __shared__ float s_z [64][32];
    __shared__ float s_B [64][8];
    __shared__ float s_C [64][8];

    int t = threadIdx.x, dl = t >> 3, n = t & 7;
    int b = blockIdx.y, dir = blockIdx.z, dblk = blockIdx.x;
    int d = dblk * 32 + dl;

    const float* Alog = dir ? Alog_b : Alog_f;
    float a_dn = -__expf(Alog[d * 8 + n]);
    float Dv   = (dir ? Db : Dp)[d];

    const float* dtp  = (dir ? g_dt1 : g_dt0) + ((size_t)b * 4096) * 256 + dblk * 32;
    const float* xp   = (dir ? g_xc1 : g_xc0) + ((size_t)b * 4096) * 256 + dblk * 32;
    const float* dblp = (dir ? g_dbl1 : g_dbl0) + ((size_t)b * 4096) * 32;
    const float* zp   = g_zs + ((size_t)b * 4096) * 256 + dblk * 32;
    float*       yp   = (dir ? g_y1 : g_y0) + ((size_t)b * 4096) * 256 + dblk * 32;

    float h = 0.f;
    for (int l0 = 0; l0 < 4096; l0 += 64) {
        __syncthreads();
#pragma unroll
        for (int rep = 0; rep < 8; rep++) {
            int li = rep * 8 + (t >> 5), di = t & 31, l = l0 + li;
            s_dt[li][di] = dtp[(size_t)l * 256 + di];
            s_x [li][di] = xp [(size_t)l * 256 + di];
            int g = dir ? (4095 - l) : l;
            s_z [li][di] = zp[(size_t)g * 256 + di];
        }
#pragma unroll
        for (int rep = 0; rep < 4; rep++) {
            int idx = rep * 256 + t, li = idx >> 4, j = idx & 15;
            float v = dblp[(size_t)(l0 + li) * 32 + 16 + j];
            if (j < 8) s_B[li][j] = v; else s_C[li][j - 8] = v;
        }
        __syncthreads();
#pragma unroll 4
        for (int li = 0; li < 64; li++) {
            float dtv = s_dt[li][dl], xv = s_x[li][dl];
            float dA = __expf(dtv * a_dn);
            h = h * dA + (dtv * xv) * s_B[li][n];
            float yv = h * s_C[li][n];
            yv += __shfl_xor_sync(0xffffffffu, yv, 1);
            yv += __shfl_xor_sync(0xffffffffu, yv, 2);
            yv += __shfl_xor_sync(0xffffffffu, yv, 4);
            if (n == 0) {
                int l = l0 + li, g = dir ? (4095 - l) : l;
                yp[(size_t)g * 256 + dl] = (yv + xv * Dv) * s_z[li][dl];
            }
        }
    }
}

// ---------------- SIMT fp32 GEMM, both directions via blockIdx.z -------------
// C[m,n] = sum_k A[m,k]*W[n,k].  EPI: 0 plain  2 +bias softplus
template<int EPI>
__global__ __launch_bounds__(256) void gemm2_kernel(
    const float* __restrict__ A0, const float* __restrict__ A1, int lda,
    const float* __restrict__ W0, const float* __restrict__ W1, int ldw,
    int M, int N, int Kact,
    float* __restrict__ C0, float* __restrict__ C1,
    const float* __restrict__ bias0, const float* __restrict__ bias1)
{
    const float* A = blockIdx.z ? A1 : A0;
    const float* W = blockIdx.z ? W1 : W0;
    float*       C = blockIdx.z ? C1 : C0;
    const float* bias = blockIdx.z ? bias1 : bias0;

    __shared__ float As[16][128];
    __shared__ float Bs[16][64];
    int t = threadIdx.x;
    int m0 = blockIdx.y * 128, n0 = blockIdx.x * 64;
    int tx = t & 15, ty = t >> 4, tm = ty * 8, tn = tx * 4;
    int k4 = (t & 3) * 4, rA = t >> 2;

    float acc[8][4];
#pragma unroll
    for (int i = 0; i < 8; i++)
#pragma unroll
        for (int j = 0; j < 4; j++) acc[i][j] = 0.f;

    for (int k0 = 0; k0 < Kact; k0 += 16) {
#pragma unroll
        for (int pass = 0; pass < 2; pass++) {
            int mi = pass * 64 + rA, gm = m0 + mi;
            float4 v = make_float4(0.f,0.f,0.f,0.f);
            if (gm < M) v = *(const float4*)(A + (size_t)gm * lda + k0 + k4);
            As[k4+0][mi]=v.x; As[k4+1][mi]=v.y; As[k4+2][mi]=v.z; As[k4+3][mi]=v.w;
        }
        {
            int gn = n0 + rA;
            float4 v = make_float4(0.f,0.f,0.f,0.f);
            if (gn < N) v = *(const float4*)(W + (size_t)gn * ldw + k0 + k4);
            Bs[k4+0][rA]=v.x; Bs[k4+1][rA]=v.y; Bs[k4+2][rA]=v.z; Bs[k4+3][rA]=v.w;
        }
        __syncthreads();
#pragma unroll
        for (int kk = 0; kk < 16; kk++) {
            float4 a0 = *(const float4*)&As[kk][tm];
            float4 a1 = *(const float4*)&As[kk][tm + 4];
            float4 bv = *(const float4*)&Bs[kk][tn];
            float ar[8] = {a0.x,a0.y,a0.z,a0.w,a1.x,a1.y,a1.z,a1.w};
            float br[4] = {bv.x,bv.y,bv.z,bv.w};
#pragma unroll
            for (int i = 0; i < 8; i++)
#pragma unroll
                for (int j = 0; j < 4; j++)
                    acc[i][j] = fmaf(ar[i], br[j], acc[i][j]);
        }
        __syncthreads();
    }
#pragma unroll
    for (int i = 0; i < 8; i++) {
        int m = m0 + tm + i;
        if (m >= M) continue;
#pragma unroll
        for (int j = 0; j < 4; j++) {
            int n = n0 + tn + j;
            if (n >= N) continue;
            float v = acc[i][j];
            if (EPI == 0) C[(size_t)m * N + n] = v;
            else { v += bias[n]; C[(size_t)m * N + n] = (v > 20.f) ? v : log1pf(__expf(v)); }
        }
    }
}

// ---------------- warp-MMA bf16-split GEMM, cp.async double-buffered ---------
// Tile 128x64, K=256, BK=32, 8 warps 4x2, 3 CTAs/SM target (<=80 regs).
// EPI: 0 plain fp32   1 silu fp32
//      3 o = v*rs[z][m] + skipT -> bf16 split into Coh/Col (+z*SZ)
//      4 out[z][b,oc,l] = v + bias[oc]
//      5 z==0: plain to C (g_x); z==1: silu to outp (g_zs)
#define STG_B 30720u
#define HMMA_SMEM (2*STG_B)
#define oAh 0u
#define oAl 10240u
#define oBh 20480u
#define oBl 25600u
#define ROWB 80u

template<int EPI>
__global__ __launch_bounds__(256, 3) void hmma_gemm(
    const __nv_bfloat16* __restrict__ Ah, const __nv_bfloat16* __restrict__ Al,
    const __nv_bfloat16* __restrict__ Bh, const __nv_bfloat16* __restrict__ Bl,
    size_t sA, size_t sB, int Ntot,
    float* __restrict__ C,
    __nv_bfloat16* __restrict__ Coh, __nv_bfloat16* __restrict__ Col,
    const float* __restrict__ rs, const float* __restrict__ skipT,
    const float* __restrict__ bias, float* __restrict__ outp)
{
    extern __shared__ char sb[];
    uint32_t sb0 = smem_u32(sb);

    int t = threadIdx.x, wid = t >> 5, lane = t & 31;
    int wm = wid & 3, wn = wid >> 2;
    int m0 = blockIdx.y * 128, n0 = blockIdx.x * 64;
    int z  = blockIdx.z;

    const uint4* A4h = (const uint4*)(Ah + (size_t)z * sA);
    const uint4* A4l = (const uint4*)(Al + (size_t)z * sA);
    const uint4* B4h = (const uint4*)(Bh + (size_t)z * sB);
    const uint4* B4l = (const uint4*)(Bl + (size_t)z * sB);

    float acc[2][4][4];
#pragma unroll
    for (int a = 0; a < 2; a++)
#pragma unroll
        for (int b = 0; b < 4; b++)
#pragma unroll
            for (int c = 0; c < 4; c++) acc[a][b][c] = 0.f;

    uint32_t rAh[2], rBh[2];
#pragma unroll
    for (int mt = 0; mt < 2; mt++)
        rAh[mt] = (uint32_t)(wm*32 + mt*16 + (lane & 15)) * ROWB + ((lane >> 4) & 1) * 16u;
#pragma unroll
    for (int nt = 0; nt < 2; nt++) {
        uint32_t row = (uint32_t)(wn*32 + nt*16 + (lane & 7) + ((lane >> 4) & 1) * 8);
        rBh[nt] = row * ROWB + ((lane >> 3) & 1) * 16u;
    }

    auto issue_chunk = [&](int kc, int stg) {
        uint32_t sbase = sb0 + (uint32_t)stg * STG_B;
#pragma unroll
        for (int i = 0; i < 2; i++) {
            int u = t + i * 256, r = u >> 2, jj = u & 3;
            size_t gidx = (size_t)(m0 + r) * 32 + kc * 4 + jj;
            uint32_t so = (uint32_t)r * ROWB + jj * 16u;
            CP_ASYNC16(sbase + oAh + so, A4h + gidx);
            CP_ASYNC16(sbase + oAl + so, A4l + gidx);
        }
        {
            int r = t >> 2, jj = t & 3;
            size_t gidx = (size_t)(n0 + r) * 32 + kc * 4 + jj;
            uint32_t so = (uint32_t)r * ROWB + jj * 16u;
            CP_ASYNC16(sbase + oBh + so, B4h + gidx);
            CP_ASYNC16(sbase + oBl + so, B4l + gidx);
        }
        CP_COMMIT();
    };

    issue_chunk(0, 0);
    for (int kc = 0; kc < 8; kc++) {
        if (kc < 7) { issue_chunk(kc + 1, (kc + 1) & 1); CP_WAIT1(); }
        else        { CP_WAIT0(); }
        __syncthreads();

        uint32_t sbase = sb0 + (uint32_t)(kc & 1) * STG_B;
#pragma unroll
        for (int ks = 0; ks < 2; ks++) {
            uint32_t kb = ks * 32u;
            uint32_t fah[2][4], fal[2][4];
#pragma unroll
            for (int mt = 0; mt < 2; mt++) {
                LDSM4(fah[mt], sbase + oAh + rAh[mt] + kb);
                LDSM4(fal[mt], sbase + oAl + rAh[mt] + kb);
            }
#pragma unroll
            for (int nt = 0; nt < 2; nt++) {
                uint32_t fbh[4], fbl[4];
                LDSM4(fbh, sbase + oBh + rBh[nt] + kb);
                LDSM4(fbl, sbase + oBl + rBh[nt] + kb);
#pragma unroll
                for (int mt = 0; mt < 2; mt++)
#pragma unroll
                    for (int hf = 0; hf < 2; hf++) {
                        int nn = nt * 2 + hf;
                        MMA16816(acc[mt][nn], fah[mt], &fbh[hf*2]);
                        MMA16816(acc[mt][nn], fah[mt], &fbl[hf*2]);
                        MMA16816(acc[mt][nn], fal[mt], &fbh[hf*2]);
                    }
            }
        }
        __syncthreads();
    }

    // stage accumulators to smem fp32 [128][64]
    float* smemf = (float*)sb;
#pragma unroll
    for (int mt = 0; mt < 2; mt++)
#pragma unroll
        for (int nn = 0; nn < 4; nn++) {
            int row = wm*32 + mt*16 + (lane >> 2);
            int col = wn*32 + nn*8 + (lane & 3) * 2;
            smemf[row * 64 + col]       = acc[mt][nn][0];
            smemf[row * 64 + col + 1]   = acc[mt][nn][1];
            smemf[(row+8) * 64 + col]   = acc[mt][nn][2];
            smemf[(row+8) * 64 + col+1] = acc[mt][nn][3];
        }
    __syncthreads();

#pragma unroll
    for (int p = 0; p < 8; p++) {
        int row = p * 16 + (t >> 4);
        int c4  = (t & 15) * 4;
        float4 v = *(float4*)&smemf[row * 64 + c4];
        int m = m0 + row;
        if (EPI == 0) {
            *(float4*)&C[(size_t)m * Ntot + n0 + c4] = v;
        } else if (EPI == 1) {
            float4 o;
            o.x = v.x / (1.f + __expf(-v.x));
            o.y = v.y / (1.f + __expf(-v.y));
            o.z = v.z / (1.f + __expf(-v.z));
            o.w = v.w / (1.f + __expf(-v.w));
            *(float4*)&C[(size_t)m * Ntot + n0 + c4] = o;
        } else if (EPI == 3) {
            float rsm = rs[(size_t)z * (Bsz*Lsz) + m];
            size_t base = (size_t)m * 256 + n0 + c4;
            size_t obase = (size_t)z * SZ + base;
            float fv[4] = {v.x, v.y, v.z, v.w};
#pragma unroll
            for (int j = 0; j < 4; j++) {
                float f = fv[j] * rsm + skipT[base + j];
                bsplit(f, Coh, Col, obase + j);
            }
        } else if (EPI == 4) {
            if (m < OUTC) {
                int tok = n0 + c4, bb = tok >> 12, l = tok & 4095;
                float bv = bias[m];
                float4 o = make_float4(v.x + bv, v.y + bv, v.z + bv, v.w + bv);
                *(float4*)&outp[(size_t)z * HEADSZ +
                                ((size_t)(bb * OUTC + m)) * 4096 + l] = o;
            }
        } else { // EPI == 5 : z0 -> plain C, z1 -> silu outp
            if (z == 0) {
                *(float4*)&C[(size_t)m * Ntot + n0 + c4] = v;
            } else {
                float4 o;
                o.x = v.x / (1.f + __expf(-v.x));
                o.y = v.y / (1.f + __expf(-v.y));
                o.z = v.z / (1.f + __expf(-v.z));
                o.w = v.w / (1.f + __expf(-v.w));
                *(float4*)&outp[(size_t)m * Ntot + n0 + c4] = o;
            }
        }
    }
}

// ---------------- weight conversion (fold rms_w, pad conv3d) -----------------
__global__ __launch_bounds__(256) void wcvt_kernel(
    const float* __restrict__ ipw, const float* __restrict__ izw,
    const float* __restrict__ opw, const float* __restrict__ rmsw,
    const float* __restrict__ c3w)
{
    int i = blockIdx.x * 256 + threadIdx.x;   // 524288 total
    float v; __nv_bfloat16 *ph, *pl; int off;
    if (i < 65536)        { off = i;          v = ipw[off];                    ph = g_ipzh; pl = g_ipzl; }
    else if (i < 131072)  { off = i;          v = izw[i - 65536];              ph = g_ipzh; pl = g_ipzl; }
    else if (i < 196608)  { off = i - 131072; v = opw[off] * rmsw[off & 255];  ph = g_wph;  pl = g_wpl; }
    else                  { off = i - 196608; int r = off >> 8;
                            v = (r < OUTC) ? c3w[off] : 0.f;                   ph = g_c3h;  pl = g_c3l; }
    bsplit(v, ph, pl, off);
}

// ---------------- y prep: avg + rms scales + bf16 splits (fused) -------------
__global__ __launch_bounds__(256) void yprep_kernel(float* __restrict__ rs3)
{
    int row  = blockIdx.x * 8 + (threadIdx.x >> 5);   // 0..8191
    int lane = threadIdx.x & 31;
    size_t base = (size_t)row * 256;

    float a[8], b[8], m[8];
    float sa = 0.f, sbv = 0.f, sm = 0.f;
#pragma unroll
    for (int j = 0; j < 8; j++) {
        size_t i = base + lane + 32 * j;
        float va = g_y0[i], vb = g_y1[i];
        float vm = 0.5f * (va + vb);
        a[j] = va; b[j] = vb; m[j] = vm;
        sa += va * va; sbv += vb * vb; sm += vm * vm;
    }
#pragma unroll
    for (int o = 16; o; o >>= 1) {
        sa  += __shfl_xor_sync(0xffffffffu, sa,  o);
        sbv += __shfl_xor_sync(0xffffffffu, sbv, o);
        sm  += __shfl_xor_sync(0xffffffffu, sm,  o);
    }
    if (lane == 0) {
        rs3[row]                 = rsqrtf(sm  * (1.0f/256.0f) + 1e-5f);
        rs3[Bsz*Lsz + row]       = rsqrtf(sa  * (1.0f/256.0f) + 1e-5f);
        rs3[2*Bsz*Lsz + row]     = rsqrtf(sbv * (1.0f/256.0f) + 1e-5f);
    }
#pragma unroll
    for (int j = 0; j < 8; j++) {
        size_t i = base + lane + 32 * j;
        bsplit(m[j], g_ysh, g_ysl, i);
        bsplit(a[j], g_ysh, g_ysl, (size_t)SZ + i);
        bsplit(b[j], g_ysh, g_ysl, (size_t)2*SZ + i);
    }
}

// ---------------- host launcher ----------------------------------------------
#define DEVPTR(ty, sym) ([&]() { void* p_ = nullptr; cudaGetSymbolAddress(&p_, sym); return (ty*)p_; }())

extern "C" void kernel_launch(void* const* d_in, const int* in_sizes, int n_in,
                              void* d_out, int out_size)
{
    (void)in_sizes; (void)n_in; (void)out_size;
    const float* in0        = (const float*)d_in[0];
    const float* in1        = (const float*)d_in[1];
    const float* norm0_w    = (const float*)d_in[2];
    const float* norm0_b    = (const float*)d_in[3];
    const float* norm1_w    = (const float*)d_in[4];
    const float* norm1_b    = (const float*)d_in[5];
    const float* in_proj_w  = (const float*)d_in[6];
    const float* in_projz_w = (const float*)d_in[7];
    const float* conv1d_w   = (const float*)d_in[8];
    const float* conv1d_b   = (const float*)d_in[9];
    const float* conv1db_w  = (const float*)d_in[10];
    const float* conv1db_b  = (const float*)d_in[11];
    const float* xproj_w    = (const float*)d_in[12];
    const float* xprojb_w   = (const float*)d_in[13];
    const float* dtproj_w   = (const float*)d_in[14];
    const float* dtproj_b   = (const float*)d_in[15];
    const float* dtprojb_w  = (const float*)d_in[16];
    const float* dtprojb_b  = (const float*)d_in[17];
    const float* A_log      = (const float*)d_in[18];
    const float* Ab_log     = (const float*)d_in[19];
    const float* D_p        = (const float*)d_in[20];
    const float* D_b        = (const float*)d_in[21];
    const float* rms_w      = (const float*)d_in[22];
    const float* out_proj_w = (const float*)d_in[23];
    const float* conv3d_w   = (const float*)d_in[24];
    const float* conv3d_b   = (const float*)d_in[25];
    float* out = (float*)d_out;

    float* p_x    = DEVPTR(float, g_x);
    float* p_zs   = DEVPTR(float, g_zs);
    float* p_xc0  = DEVPTR(float, g_xc0);
    float* p_xc1  = DEVPTR(float, g_xc1);
    float* p_dbl0 = DEVPTR(float, g_dbl0);
    float* p_dbl1 = DEVPTR(float, g_dbl1);
    float* p_dt0  = DEVPTR(float, g_dt0);
    float* p_dt1  = DEVPTR(float, g_dt1);
    float* p_skT  = DEVPTR(float, g_skipT);
    float* p_rs3  = DEVPTR(float, g_rs3);

    __nv_bfloat16* p_sAh = DEVPTR(__nv_bfloat16, g_sAh);
    __nv_bfloat16* p_sAl = DEVPTR(__nv_bfloat16, g_sAl);
    __nv_bfloat16* p_ysh = DEVPTR(__nv_bfloat16, g_ysh);
    __nv_bfloat16* p_ysl = DEVPTR(__nv_bfloat16, g_ysl);
    __nv_bfloat16* p_oh3 = DEVPTR(__nv_bfloat16, g_oh3);
    __nv_bfloat16* p_ol3 = DEVPTR(__nv_bfloat16, g_ol3);
    __nv_bfloat16* p_ipzh = DEVPTR(__nv_bfloat16, g_ipzh);
    __nv_bfloat16* p_ipzl = DEVPTR(__nv_bfloat16, g_ipzl);
    __nv_bfloat16* p_wph = DEVPTR(__nv_bfloat16, g_wph);
    __nv_bfloat16* p_wpl = DEVPTR(__nv_bfloat16, g_wpl);
    __nv_bfloat16* p_c3h = DEVPTR(__nv_bfloat16, g_c3h);
    __nv_bfloat16* p_c3l = DEVPTR(__nv_bfloat16, g_c3l);

    cudaFuncSetAttribute(hmma_gemm<3>, cudaFuncAttributeMaxDynamicSharedMemorySize, HMMA_SMEM);
    cudaFuncSetAttribute(hmma_gemm<4>, cudaFuncAttributeMaxDynamicSharedMemorySize, HMMA_SMEM);
    cudaFuncSetAttribute(hmma_gemm<5>, cudaFuncAttributeMaxDynamicSharedMemorySize, HMMA_SMEM);

    // 0. weight conversion (independent)
    wcvt_kernel<<<2048, 256>>>(in_proj_w, in_projz_w, out_proj_w, rms_w, conv3d_w);

    // 1. layernorm + transpose + split (+skipT)
    ln_kernel<<<dim3(128, 2, 2), 256>>>(in0, norm0_w, norm0_b, in1, norm1_w, norm1_b);

    // 2. in_proj & in_projz in ONE launch (EPI5: z0->g_x, z1->silu g_zs)
    hmma_gemm<5><<<dim3(4, 64, 2), 256, HMMA_SMEM>>>(p_sAh, p_sAl, p_ipzh, p_ipzl,
        (size_t)SZ, (size_t)WSZ, 256,
        p_x, nullptr, nullptr, nullptr, nullptr, nullptr, p_zs);

    // 3. depthwise conv + silu
    conv_kernel<<<dim3(256, 2, 2), 256>>>(conv1d_w, conv1d_b, conv1db_w, conv1db_b);

    // 4. xproj both dirs (SIMT, z=2)
    gemm2_kernel<0><<<dim3(1, 64, 2), 256>>>(p_xc0, p_xc1, 256, xproj_w, xprojb_w, 256,
        8192, 32, 256, p_dbl0, p_dbl1, nullptr, nullptr);

    // 5. dtproj + softplus both dirs (SIMT, z=2)
    gemm2_kernel<2><<<dim3(4, 64, 2), 256>>>(p_dbl0, p_dbl1, 32, dtproj_w, dtprojb_w, 16,
        8192, 256, 16, p_dt0, p_dt1, dtproj_b, dtprojb_b);

    // 6. sequential scan
    scan_kernel<<<dim3(8, 2, 2), 256>>>(A_log, Ab_log, D_p, D_b);

    // 7. fused avg + rms scales + bf16 splits
    yprep_kernel<<<1024, 256>>>(p_rs3);

    // 8. heads: out_proj(+skip) then conv3d, all 3 heads per launch
    hmma_gemm<3><<<dim3(4, 64, 3), 256, HMMA_SMEM>>>(p_ysh, p_ysl, p_wph, p_wpl,
        (size_t)SZ, 0, 256,
        nullptr, p_oh3, p_ol3, p_rs3, p_skT, nullptr, nullptr);
    hmma_gemm<4><<<dim3(128, 10, 3), 256, HMMA_SMEM>>>(p_c3h, p_c3l, p_oh3, p_ol3,
        0, (size_t)SZ, 256,
        nullptr, nullptr, nullptr, nullptr, nullptr, conv3d_b, out);
}